// round 1
// baseline (speedup 1.0000x reference)
#include <cuda_runtime.h>
#include <cstdint>

// Problem constants
#define NB   8
#define TT   2048
#define CC   1024
#define MM   (NB*TT)      // 16384 rows

// Scratch (allocation-free rule: static __device__ arrays)
__device__ float g_k[(size_t)MM * CC];
__device__ float g_v[(size_t)MM * CC];
__device__ float g_r[(size_t)MM * CC];   // r in, then y = wkv*sigmoid(r) in place

// ---------------------------------------------------------------------------
// Tiled fp32 GEMM:  C[m][j] = sum_c A(m,c) * W[j][c]   (both row-major, K inner)
// A(m,c) = MIX ? x[m][c]*tm[c] + lastx[n][c]*(1-tm[c]) : A[m][c]
// BM=BN=128, BK=16, 256 threads, 8x8 per-thread microtile.
// ---------------------------------------------------------------------------
template<bool MIX>
__global__ void __launch_bounds__(256, 2)
gemm128(const float* __restrict__ A, const float* __restrict__ W,
        float* __restrict__ Cout,
        const float* __restrict__ tm, const float* __restrict__ lastx)
{
    __shared__ float As[16][128];
    __shared__ float Bs[16][128];

    const int tid = threadIdx.x;
    const int M0 = blockIdx.y * 128;
    const int N0 = blockIdx.x * 128;
    const int nbat = M0 / TT;          // batch index (tile never crosses batch: TT%128==0)
    const int K = CC;

    const int lrow = tid >> 2;         // 0..63
    const int lcol = (tid & 3) * 4;    // 0,4,8,12

    const int ty = tid >> 4;           // 0..15
    const int tx = tid & 15;           // 0..15

    float acc[8][8];
    #pragma unroll
    for (int i = 0; i < 8; i++)
        #pragma unroll
        for (int j = 0; j < 8; j++) acc[i][j] = 0.f;

    for (int k0 = 0; k0 < K; k0 += 16) {
        // --- load A tile (with fused mixing) ---
        #pragma unroll
        for (int rr = 0; rr < 2; rr++) {
            const int m = M0 + lrow + rr * 64;
            float4 av = *(const float4*)(&A[(size_t)m * K + k0 + lcol]);
            if (MIX) {
                const float4 t4 = *(const float4*)(&tm[k0 + lcol]);
                const float4 l4 = *(const float4*)(&lastx[(size_t)nbat * K + k0 + lcol]);
                av.x = av.x * t4.x + l4.x * (1.f - t4.x);
                av.y = av.y * t4.y + l4.y * (1.f - t4.y);
                av.z = av.z * t4.z + l4.z * (1.f - t4.z);
                av.w = av.w * t4.w + l4.w * (1.f - t4.w);
            }
            As[lcol + 0][lrow + rr * 64] = av.x;
            As[lcol + 1][lrow + rr * 64] = av.y;
            As[lcol + 2][lrow + rr * 64] = av.z;
            As[lcol + 3][lrow + rr * 64] = av.w;
        }
        // --- load B tile (weights) ---
        #pragma unroll
        for (int rr = 0; rr < 2; rr++) {
            const int j = N0 + lrow + rr * 64;
            const float4 bv = *(const float4*)(&W[(size_t)j * K + k0 + lcol]);
            Bs[lcol + 0][lrow + rr * 64] = bv.x;
            Bs[lcol + 1][lrow + rr * 64] = bv.y;
            Bs[lcol + 2][lrow + rr * 64] = bv.z;
            Bs[lcol + 3][lrow + rr * 64] = bv.w;
        }
        __syncthreads();

        #pragma unroll
        for (int kk = 0; kk < 16; kk++) {
            float af[8], bf[8];
            #pragma unroll
            for (int i = 0; i < 4; i++) {
                ((float4*)af)[0] = *(const float4*)(&As[kk][ty * 8]);
                ((float4*)af)[1] = *(const float4*)(&As[kk][ty * 8 + 4]);
                ((float4*)bf)[0] = *(const float4*)(&Bs[kk][tx * 8]);
                ((float4*)bf)[1] = *(const float4*)(&Bs[kk][tx * 8 + 4]);
                break;
            }
            #pragma unroll
            for (int i = 0; i < 8; i++)
                #pragma unroll
                for (int j = 0; j < 8; j++)
                    acc[i][j] += af[i] * bf[j];
        }
        __syncthreads();
    }

    #pragma unroll
    for (int i = 0; i < 8; i++) {
        const int m = M0 + ty * 8 + i;
        float4* dst = (float4*)&Cout[(size_t)m * CC + N0 + tx * 8];
        dst[0] = make_float4(acc[i][0], acc[i][1], acc[i][2], acc[i][3]);
        dst[1] = make_float4(acc[i][4], acc[i][5], acc[i][6], acc[i][7]);
    }
}

// ---------------------------------------------------------------------------
// wkv scan: one thread per (batch, channel). Sequential over T.
// Fuses y = wkv * sigmoid(r) in place into g_r.
// ---------------------------------------------------------------------------
__global__ void __launch_bounds__(64)
wkv_scan(const float* __restrict__ kbuf, const float* __restrict__ vbuf,
         float* __restrict__ rbuf,
         const float* __restrict__ time_decay, const float* __restrict__ time_first,
         const float* __restrict__ state)
{
    const int ch = blockIdx.x * blockDim.x + threadIdx.x;   // 0..8191
    if (ch >= NB * CC) return;
    const int n = ch >> 10;
    const int c = ch & (CC - 1);

    const float u = time_first[c];
    const float w = __expf(time_decay[c]);

    const float* st = state + (size_t)n * 3 * CC;
    float a = st[c];
    float b = st[CC + c];
    float e = st[2 * CC + c];

    size_t idx = (size_t)n * TT * CC + c;
    #pragma unroll 4
    for (int t = 0; t < TT; t++, idx += CC) {
        const float kt = kbuf[idx];
        const float vt = vbuf[idx];

        const float ukt = u + kt;
        const float tau = fmaxf(ukt, e);
        const float e1  = __expf(e - tau);
        const float e2  = __expf(ukt - tau);
        const float wkv = (e1 * a + e2 * vt) / (e1 * b + e2);

        const float rr = rbuf[idx];
        const float sr = 1.f / (1.f + __expf(-rr));
        rbuf[idx] = wkv * sr;

        const float we  = e - w;
        const float en  = fmaxf(we, kt);
        const float e1n = __expf(we - en);
        const float e2n = __expf(kt - en);
        a = e1n * a + e2n * vt;
        b = e1n * b + e2n;
        e = en;
    }
}

// ---------------------------------------------------------------------------
// Launch
// ---------------------------------------------------------------------------
extern "C" void kernel_launch(void* const* d_in, const int* in_sizes, int n_in,
                              void* d_out, int out_size)
{
    const float* x      = (const float*)d_in[0];
    // d_in[1] = it (unused)
    const float* Wk     = (const float*)d_in[2];
    const float* Wv     = (const float*)d_in[3];
    const float* Wr     = (const float*)d_in[4];
    const float* Wo     = (const float*)d_in[5];
    const float* tmk    = (const float*)d_in[6];
    const float* tmv    = (const float*)d_in[7];
    const float* tmr    = (const float*)d_in[8];
    const float* td     = (const float*)d_in[9];
    const float* tf     = (const float*)d_in[10];
    const float* lastx  = (const float*)d_in[11];
    const float* state  = (const float*)d_in[12];
    float* out = (float*)d_out;

    float *kp, *vp, *rp;
    cudaGetSymbolAddress((void**)&kp, g_k);
    cudaGetSymbolAddress((void**)&vp, g_v);
    cudaGetSymbolAddress((void**)&rp, g_r);

    dim3 grid(CC / 128, MM / 128);
    gemm128<true><<<grid, 256>>>(x, Wk, kp, tmk, lastx);
    gemm128<true><<<grid, 256>>>(x, Wv, vp, tmv, lastx);
    gemm128<true><<<grid, 256>>>(x, Wr, rp, tmr, lastx);

    wkv_scan<<<(NB * CC + 63) / 64, 64>>>(kp, vp, rp, td, tf, state);

    gemm128<false><<<grid, 256>>>(rp, Wo, out, nullptr, nullptr);
}

// round 3
// speedup vs baseline: 1.6124x; 1.6124x over previous
#include <cuda_runtime.h>
#include <cuda_bf16.h>
#include <cstdint>

#define NB 8
#define TT 2048
#define CC 1024
#define MM (NB*TT)          // 16384

// ---------------- scratch (static __device__; no allocation) ----------------
__device__ __align__(256) float g_k[(size_t)MM*CC];
__device__ __align__(256) float g_v[(size_t)MM*CC];
__device__ __align__(256) float g_r[(size_t)MM*CC];

__device__ __align__(256) __nv_bfloat16 g_kh[(size_t)MM*CC], g_kl[(size_t)MM*CC];
__device__ __align__(256) __nv_bfloat16 g_vh[(size_t)MM*CC], g_vl[(size_t)MM*CC];
__device__ __align__(256) __nv_bfloat16 g_rh[(size_t)MM*CC], g_rl[(size_t)MM*CC];
__device__ __align__(256) __nv_bfloat16 g_yh[(size_t)MM*CC], g_yl[(size_t)MM*CC];

__device__ __align__(256) __nv_bfloat16 g_Wkh[CC*CC], g_Wkl[CC*CC];
__device__ __align__(256) __nv_bfloat16 g_Wvh[CC*CC], g_Wvl[CC*CC];
__device__ __align__(256) __nv_bfloat16 g_Wrh[CC*CC], g_Wrl[CC*CC];
__device__ __align__(256) __nv_bfloat16 g_Woh[CC*CC], g_Wol[CC*CC];

// ---------------- PTX helpers (architecture-stable, sm_80-era) ----------------
__device__ __forceinline__ uint32_t smem_u32(const void* p) {
    uint32_t a;
    asm("{ .reg .u64 t; cvta.to.shared.u64 t, %1; cvt.u32.u64 %0, t; }" : "=r"(a) : "l"(p));
    return a;
}
__device__ __forceinline__ void cp16(uint32_t saddr, const void* g) {
    asm volatile("cp.async.cg.shared.global [%0], [%1], 16;" :: "r"(saddr), "l"(g));
}
__device__ __forceinline__ void cp_commit() {
    asm volatile("cp.async.commit_group;" ::: "memory");
}
template<int N> __device__ __forceinline__ void cp_wait() {
    asm volatile("cp.async.wait_group %0;" :: "n"(N) : "memory");
}
__device__ __forceinline__ void ldsm4(uint32_t* r, uint32_t addr) {
    asm volatile("ldmatrix.sync.aligned.m8n8.x4.shared.b16 {%0,%1,%2,%3}, [%4];"
                 : "=r"(r[0]), "=r"(r[1]), "=r"(r[2]), "=r"(r[3]) : "r"(addr));
}
__device__ __forceinline__ void mma_bf16(float* c, const uint32_t* a, uint32_t b0, uint32_t b1) {
    asm volatile(
        "mma.sync.aligned.m16n8k16.row.col.f32.bf16.bf16.f32 "
        "{%0,%1,%2,%3}, {%4,%5,%6,%7}, {%8,%9}, {%0,%1,%2,%3};"
        : "+f"(c[0]), "+f"(c[1]), "+f"(c[2]), "+f"(c[3])
        : "r"(a[0]), "r"(a[1]), "r"(a[2]), "r"(a[3]), "r"(b0), "r"(b1));
}

// ---------------- GEMM: C[m][j] = sum_c A(m,c)*W(j,c), bf16x3 split ----------------
// BM=BN=128, BK=64 (128B rows, SW128 swizzle). 256 threads, warps 4(M) x 2(N).
// Warp tile 32x64: 2 m16 x 8 n8 per pass, 3 passes (AhBh, AhBl, AlBh).
#define BM 128
#define BN 128
#define BK 64
#define ASZ (BM*128)                   // 16 KB per operand tile
#define STAGE (4*ASZ)                  // AhiAloBhiBlo = 64 KB
#define NSTAGE 3
#define GEMM_SMEM (NSTAGE*STAGE)       // 192 KB

__global__ void __launch_bounds__(256, 1)
gemm_bf16x3(const __nv_bfloat16* __restrict__ Ah, const __nv_bfloat16* __restrict__ Al,
            const __nv_bfloat16* __restrict__ Bh, const __nv_bfloat16* __restrict__ Bl,
            float* __restrict__ Cout)
{
    extern __shared__ char smem[];
    const uint32_t sbase = smem_u32(smem);
    const int tid = threadIdx.x;
    const int wid = tid >> 5, lid = tid & 31;
    const int warp_m = wid & 3, warp_n = wid >> 2;
    const int M0 = blockIdx.y * BM, N0 = blockIdx.x * BN;

    float acc[2][8][4];
    #pragma unroll
    for (int i = 0; i < 2; i++)
        #pragma unroll
        for (int j = 0; j < 8; j++)
            #pragma unroll
            for (int q = 0; q < 4; q++) acc[i][j][q] = 0.f;

    auto load_stage = [&](int s) {
        const uint32_t base = sbase + (s % NSTAGE) * STAGE;
        const int k0 = s * BK;
        #pragma unroll
        for (int i = 0; i < 4; i++) {
            const int c = tid + i * 256;          // 0..1023
            const int r = c >> 3, j = c & 7;      // row, 16B chunk
            uint32_t off = r * 128 + j * 16;
            uint32_t sw = off ^ ((off >> 3) & 0x70);
            const size_t ga = ((size_t)(M0 + r) * CC + k0) * 2 + j * 16;
            const size_t gb = ((size_t)(N0 + r) * CC + k0) * 2 + j * 16;
            cp16(base + sw,           (const char*)Ah + ga);
            cp16(base + ASZ + sw,     (const char*)Al + ga);
            cp16(base + 2 * ASZ + sw, (const char*)Bh + gb);
            cp16(base + 3 * ASZ + sw, (const char*)Bl + gb);
        }
        cp_commit();
    };

    load_stage(0); load_stage(1); load_stage(2);

    const int nk = CC / BK;   // 16
    for (int s = 0; s < nk; s++) {
        if (s < nk - 2)      cp_wait<2>();
        else if (s == nk-2)  cp_wait<1>();
        else                 cp_wait<0>();
        __syncthreads();

        const uint32_t bA  = sbase + (s % NSTAGE) * STAGE;
        const uint32_t bAl = bA + ASZ;
        const uint32_t bB  = bA + 2 * ASZ;
        const uint32_t bBl = bA + 3 * ASZ;

        #pragma unroll
        for (int st = 0; st < 4; st++) {          // 4 x k16
            const int cb = st * 32 + ((lid >> 4) * 16);
            uint32_t ah[2][4], al[2][4], bh[4][4], bl[4][4];
            #pragma unroll
            for (int i = 0; i < 2; i++) {
                const int r = warp_m * 32 + i * 16 + (lid & 15);
                uint32_t off = r * 128 + cb;
                uint32_t sw = off ^ ((off >> 3) & 0x70);
                ldsm4(ah[i], bA + sw);
                ldsm4(al[i], bAl + sw);
            }
            #pragma unroll
            for (int q = 0; q < 4; q++) {
                const int r = warp_n * 64 + q * 16 + (lid & 15);
                uint32_t off = r * 128 + cb;
                uint32_t sw = off ^ ((off >> 3) & 0x70);
                ldsm4(bh[q], bB + sw);
                ldsm4(bl[q], bBl + sw);
            }
            #pragma unroll
            for (int i = 0; i < 2; i++)
                #pragma unroll
                for (int j = 0; j < 8; j++) {
                    const int q = j >> 1, h = j & 1;
                    mma_bf16(acc[i][j], ah[i], bh[q][h], bh[q][2 + h]);
                    mma_bf16(acc[i][j], ah[i], bl[q][h], bl[q][2 + h]);
                    mma_bf16(acc[i][j], al[i], bh[q][h], bh[q][2 + h]);
                }
        }
        __syncthreads();
        if (s + NSTAGE < nk) load_stage(s + NSTAGE);
    }

    // epilogue: mma C-frag layout -> global
    #pragma unroll
    for (int i = 0; i < 2; i++) {
        const int row = M0 + warp_m * 32 + i * 16 + (lid >> 2);
        #pragma unroll
        for (int j = 0; j < 8; j++) {
            const int col = N0 + warp_n * 64 + j * 8 + (lid & 3) * 2;
            *(float2*)&Cout[(size_t)row * CC + col]       = make_float2(acc[i][j][0], acc[i][j][1]);
            *(float2*)&Cout[(size_t)(row + 8) * CC + col] = make_float2(acc[i][j][2], acc[i][j][3]);
        }
    }
}

// ---------------- weight split ----------------
__global__ void __launch_bounds__(256)
split_w(const float* __restrict__ W, __nv_bfloat16* __restrict__ H,
        __nv_bfloat16* __restrict__ L, int n)
{
    int i = blockIdx.x * blockDim.x + threadIdx.x;
    if (i < n) {
        float w = W[i];
        __nv_bfloat16 h = __float2bfloat16_rn(w);
        H[i] = h;
        L[i] = __float2bfloat16_rn(w - __bfloat162float(h));
    }
}

// ---------------- mix + split ----------------
__global__ void __launch_bounds__(256)
mix_split(const float* __restrict__ x, const float* __restrict__ lastx,
          const float* __restrict__ tmk, const float* __restrict__ tmv,
          const float* __restrict__ tmr)
{
    const int i = blockIdx.x * blockDim.x + threadIdx.x;   // 0 .. MM*CC/4-1
    const int m = i >> 8;            // 256 float4 groups per row
    const int c4 = (i & 255) * 4;
    const int n = m >> 11;           // TT = 2048 rows per batch
    const size_t e = (size_t)m * CC + c4;

    const float4 xv = *(const float4*)&x[e];
    const float4 l4 = *(const float4*)&lastx[(size_t)n * CC + c4];
    const float4 tk = *(const float4*)&tmk[c4];
    const float4 tv = *(const float4*)&tmv[c4];
    const float4 tr = *(const float4*)&tmr[c4];

    const float xs[4] = {xv.x, xv.y, xv.z, xv.w};
    const float ls[4] = {l4.x, l4.y, l4.z, l4.w};
    const float tks[4] = {tk.x, tk.y, tk.z, tk.w};
    const float tvs[4] = {tv.x, tv.y, tv.z, tv.w};
    const float trs[4] = {tr.x, tr.y, tr.z, tr.w};

    struct b4 { __nv_bfloat16 v[4]; };
    b4 kh, kl, vh, vl, rh, rl;
    #pragma unroll
    for (int q = 0; q < 4; q++) {
        const float mk = xs[q] * tks[q] + ls[q] * (1.f - tks[q]);
        const float mv = xs[q] * tvs[q] + ls[q] * (1.f - tvs[q]);
        const float mr = xs[q] * trs[q] + ls[q] * (1.f - trs[q]);
        kh.v[q] = __float2bfloat16_rn(mk);
        kl.v[q] = __float2bfloat16_rn(mk - __bfloat162float(kh.v[q]));
        vh.v[q] = __float2bfloat16_rn(mv);
        vl.v[q] = __float2bfloat16_rn(mv - __bfloat162float(vh.v[q]));
        rh.v[q] = __float2bfloat16_rn(mr);
        rl.v[q] = __float2bfloat16_rn(mr - __bfloat162float(rh.v[q]));
    }
    *(b4*)&g_kh[e] = kh;  *(b4*)&g_kl[e] = kl;
    *(b4*)&g_vh[e] = vh;  *(b4*)&g_vl[e] = vl;
    *(b4*)&g_rh[e] = rh;  *(b4*)&g_rl[e] = rl;
}

// ---------------- wkv scan (fp32, fused sigmoid gate + bf16 split of y) ----------------
__global__ void __launch_bounds__(64)
wkv_scan(const float* __restrict__ kbuf, const float* __restrict__ vbuf,
         const float* __restrict__ rbuf,
         const float* __restrict__ time_decay, const float* __restrict__ time_first,
         const float* __restrict__ state)
{
    const int ch = blockIdx.x * blockDim.x + threadIdx.x;
    if (ch >= NB * CC) return;
    const int n = ch >> 10;
    const int c = ch & (CC - 1);

    const float u = time_first[c];
    const float w = __expf(time_decay[c]);

    const float* st = state + (size_t)n * 3 * CC;
    float a = st[c];
    float b = st[CC + c];
    float e = st[2 * CC + c];

    size_t idx = (size_t)n * TT * CC + c;
    #pragma unroll 4
    for (int t = 0; t < TT; t++, idx += CC) {
        const float kt = kbuf[idx];
        const float vt = vbuf[idx];

        const float ukt = u + kt;
        const float tau = fmaxf(ukt, e);
        const float e1  = __expf(e - tau);
        const float e2  = __expf(ukt - tau);
        const float wkv = (e1 * a + e2 * vt) / (e1 * b + e2);

        const float rr = rbuf[idx];
        const float sr = 1.f / (1.f + __expf(-rr));
        const float y  = wkv * sr;
        const __nv_bfloat16 yh = __float2bfloat16_rn(y);
        g_yh[idx] = yh;
        g_yl[idx] = __float2bfloat16_rn(y - __bfloat162float(yh));

        const float we  = e - w;
        const float en  = fmaxf(we, kt);
        const float e1n = __expf(we - en);
        const float e2n = __expf(kt - en);
        a = e1n * a + e2n * vt;
        b = e1n * b + e2n;
        e = en;
    }
}

// ---------------- launch ----------------
extern "C" void kernel_launch(void* const* d_in, const int* in_sizes, int n_in,
                              void* d_out, int out_size)
{
    const float* x     = (const float*)d_in[0];
    const float* Wk    = (const float*)d_in[2];
    const float* Wv    = (const float*)d_in[3];
    const float* Wr    = (const float*)d_in[4];
    const float* Wo    = (const float*)d_in[5];
    const float* tmk   = (const float*)d_in[6];
    const float* tmv   = (const float*)d_in[7];
    const float* tmr   = (const float*)d_in[8];
    const float* td    = (const float*)d_in[9];
    const float* tf    = (const float*)d_in[10];
    const float* lastx = (const float*)d_in[11];
    const float* state = (const float*)d_in[12];
    float* out = (float*)d_out;

    float *kp, *vp, *rp;
    cudaGetSymbolAddress((void**)&kp, g_k);
    cudaGetSymbolAddress((void**)&vp, g_v);
    cudaGetSymbolAddress((void**)&rp, g_r);

    __nv_bfloat16 *kh,*kl,*vh,*vl,*rh,*rl,*yh,*yl;
    cudaGetSymbolAddress((void**)&kh, g_kh); cudaGetSymbolAddress((void**)&kl, g_kl);
    cudaGetSymbolAddress((void**)&vh, g_vh); cudaGetSymbolAddress((void**)&vl, g_vl);
    cudaGetSymbolAddress((void**)&rh, g_rh); cudaGetSymbolAddress((void**)&rl, g_rl);
    cudaGetSymbolAddress((void**)&yh, g_yh); cudaGetSymbolAddress((void**)&yl, g_yl);

    __nv_bfloat16 *wkh,*wkl,*wvh,*wvl,*wrh,*wrl,*woh,*wol;
    cudaGetSymbolAddress((void**)&wkh, g_Wkh); cudaGetSymbolAddress((void**)&wkl, g_Wkl);
    cudaGetSymbolAddress((void**)&wvh, g_Wvh); cudaGetSymbolAddress((void**)&wvl, g_Wvl);
    cudaGetSymbolAddress((void**)&wrh, g_Wrh); cudaGetSymbolAddress((void**)&wrl, g_Wrl);
    cudaGetSymbolAddress((void**)&woh, g_Woh); cudaGetSymbolAddress((void**)&wol, g_Wol);

    cudaFuncSetAttribute(gemm_bf16x3, cudaFuncAttributeMaxDynamicSharedMemorySize, GEMM_SMEM);

    const int nW = CC * CC;
    split_w<<<(nW + 255) / 256, 256>>>(Wk, wkh, wkl, nW);
    split_w<<<(nW + 255) / 256, 256>>>(Wv, wvh, wvl, nW);
    split_w<<<(nW + 255) / 256, 256>>>(Wr, wrh, wrl, nW);
    split_w<<<(nW + 255) / 256, 256>>>(Wo, woh, wol, nW);

    mix_split<<<(MM * CC / 4 + 255) / 256, 256>>>(x, lastx, tmk, tmv, tmr);

    dim3 grid(CC / BN, MM / BM);   // (8, 128)
    gemm_bf16x3<<<grid, 256, GEMM_SMEM>>>(kh, kl, wkh, wkl, kp);
    gemm_bf16x3<<<grid, 256, GEMM_SMEM>>>(vh, vl, wvh, wvl, vp);
    gemm_bf16x3<<<grid, 256, GEMM_SMEM>>>(rh, rl, wrh, wrl, rp);

    wkv_scan<<<(NB * CC + 63) / 64, 64>>>(kp, vp, rp, td, tf, state);

    gemm_bf16x3<<<grid, 256, GEMM_SMEM>>>(yh, yl, woh, wol, out);
}

// round 4
// speedup vs baseline: 2.0906x; 1.2966x over previous
#include <cuda_runtime.h>
#include <cuda_fp16.h>
#include <cstdint>

#define NB 8
#define TT 2048
#define CC 1024
#define MM (NB*TT)          // 16384

// ---------------- scratch (static __device__; no allocation) ----------------
__device__ __align__(256) float g_k[(size_t)MM*CC];
__device__ __align__(256) float g_v[(size_t)MM*CC];
__device__ __align__(256) float g_r[(size_t)MM*CC];

__device__ __align__(256) __half g_kh[(size_t)MM*CC];
__device__ __align__(256) __half g_vh[(size_t)MM*CC];
__device__ __align__(256) __half g_rh[(size_t)MM*CC];
__device__ __align__(256) __half g_y [(size_t)MM*CC];

__device__ __align__(256) __half g_Wkh[CC*CC];
__device__ __align__(256) __half g_Wvh[CC*CC];
__device__ __align__(256) __half g_Wrh[CC*CC];
__device__ __align__(256) __half g_Woh[CC*CC];

// ---------------- PTX helpers (architecture-stable, sm_80-era) ----------------
__device__ __forceinline__ uint32_t smem_u32(const void* p) {
    uint32_t a;
    asm("{ .reg .u64 t; cvta.to.shared.u64 t, %1; cvt.u32.u64 %0, t; }" : "=r"(a) : "l"(p));
    return a;
}
__device__ __forceinline__ void cp16(uint32_t saddr, const void* g) {
    asm volatile("cp.async.cg.shared.global [%0], [%1], 16;" :: "r"(saddr), "l"(g));
}
__device__ __forceinline__ void cp_commit() {
    asm volatile("cp.async.commit_group;" ::: "memory");
}
template<int N> __device__ __forceinline__ void cp_wait() {
    asm volatile("cp.async.wait_group %0;" :: "n"(N) : "memory");
}
__device__ __forceinline__ void ldsm4(uint32_t* r, uint32_t addr) {
    asm volatile("ldmatrix.sync.aligned.m8n8.x4.shared.b16 {%0,%1,%2,%3}, [%4];"
                 : "=r"(r[0]), "=r"(r[1]), "=r"(r[2]), "=r"(r[3]) : "r"(addr));
}
__device__ __forceinline__ void mma_f16(float* c, const uint32_t* a, uint32_t b0, uint32_t b1) {
    asm volatile(
        "mma.sync.aligned.m16n8k16.row.col.f32.f16.f16.f32 "
        "{%0,%1,%2,%3}, {%4,%5,%6,%7}, {%8,%9}, {%0,%1,%2,%3};"
        : "+f"(c[0]), "+f"(c[1]), "+f"(c[2]), "+f"(c[3])
        : "r"(a[0]), "r"(a[1]), "r"(a[2]), "r"(a[3]), "r"(b0), "r"(b1));
}

// ---------------- GEMM: C[m][j] = sum_c A(m,c)*W(j,c), single-pass fp16 ----------------
// BM=BN=128, BK=64 (128B rows, SW128 swizzle). 256 threads, warps 4(M) x 2(N).
// Warp tile 32x64: 2 m16 x 8 n8, 1 pass.
#define BM 128
#define BN 128
#define BK 64
#define ASZ (BM*128)                   // 16 KB per operand tile
#define STAGE (2*ASZ)                  // A + B = 32 KB
#define NSTAGE 3
#define GEMM_SMEM (NSTAGE*STAGE)       // 96 KB -> 2 CTAs/SM

__global__ void __launch_bounds__(256, 2)
gemm_fp16(const __half* __restrict__ Ah, const __half* __restrict__ Bh,
          float* __restrict__ Cout)
{
    extern __shared__ char smem[];
    const uint32_t sbase = smem_u32(smem);
    const int tid = threadIdx.x;
    const int wid = tid >> 5, lid = tid & 31;
    const int warp_m = wid & 3, warp_n = wid >> 2;
    const int M0 = blockIdx.y * BM, N0 = blockIdx.x * BN;

    float acc[2][8][4];
    #pragma unroll
    for (int i = 0; i < 2; i++)
        #pragma unroll
        for (int j = 0; j < 8; j++)
            #pragma unroll
            for (int q = 0; q < 4; q++) acc[i][j][q] = 0.f;

    auto load_stage = [&](int s) {
        const uint32_t base = sbase + (s % NSTAGE) * STAGE;
        const int k0 = s * BK;
        #pragma unroll
        for (int i = 0; i < 4; i++) {
            const int c = tid + i * 256;          // 0..1023
            const int r = c >> 3, j = c & 7;      // row, 16B chunk
            uint32_t off = r * 128 + j * 16;
            uint32_t sw = off ^ ((off >> 3) & 0x70);
            const size_t ga = ((size_t)(M0 + r) * CC + k0) * 2 + j * 16;
            const size_t gb = ((size_t)(N0 + r) * CC + k0) * 2 + j * 16;
            cp16(base + sw,       (const char*)Ah + ga);
            cp16(base + ASZ + sw, (const char*)Bh + gb);
        }
        cp_commit();
    };

    load_stage(0); load_stage(1); load_stage(2);

    const int nk = CC / BK;   // 16
    for (int s = 0; s < nk; s++) {
        if (s < nk - 2)      cp_wait<2>();
        else if (s == nk-2)  cp_wait<1>();
        else                 cp_wait<0>();
        __syncthreads();

        const uint32_t bA = sbase + (s % NSTAGE) * STAGE;
        const uint32_t bB = bA + ASZ;

        #pragma unroll
        for (int st = 0; st < 4; st++) {          // 4 x k16
            const int cb = st * 32 + ((lid >> 4) * 16);
            uint32_t ah[2][4], bh[4][4];
            #pragma unroll
            for (int i = 0; i < 2; i++) {
                const int r = warp_m * 32 + i * 16 + (lid & 15);
                uint32_t off = r * 128 + cb;
                uint32_t sw = off ^ ((off >> 3) & 0x70);
                ldsm4(ah[i], bA + sw);
            }
            #pragma unroll
            for (int q = 0; q < 4; q++) {
                const int r = warp_n * 64 + q * 16 + (lid & 15);
                uint32_t off = r * 128 + cb;
                uint32_t sw = off ^ ((off >> 3) & 0x70);
                ldsm4(bh[q], bB + sw);
            }
            #pragma unroll
            for (int i = 0; i < 2; i++)
                #pragma unroll
                for (int j = 0; j < 8; j++) {
                    const int q = j >> 1, h = j & 1;
                    mma_f16(acc[i][j], ah[i], bh[q][h], bh[q][2 + h]);
                }
        }
        __syncthreads();
        if (s + NSTAGE < nk) load_stage(s + NSTAGE);
    }

    // epilogue: mma C-frag layout -> global
    #pragma unroll
    for (int i = 0; i < 2; i++) {
        const int row = M0 + warp_m * 32 + i * 16 + (lid >> 2);
        #pragma unroll
        for (int j = 0; j < 8; j++) {
            const int col = N0 + warp_n * 64 + j * 8 + (lid & 3) * 2;
            *(float2*)&Cout[(size_t)row * CC + col]       = make_float2(acc[i][j][0], acc[i][j][1]);
            *(float2*)&Cout[(size_t)(row + 8) * CC + col] = make_float2(acc[i][j][2], acc[i][j][3]);
        }
    }
}

// ---------------- weight convert fp32 -> fp16 ----------------
__global__ void __launch_bounds__(256)
conv_w(const float* __restrict__ W, __half* __restrict__ H, int n)
{
    int i = (blockIdx.x * blockDim.x + threadIdx.x) * 4;
    if (i < n) {
        const float4 w = *(const float4*)&W[i];
        struct h4 { __half v[4]; };
        h4 o;
        o.v[0] = __float2half_rn(w.x);
        o.v[1] = __float2half_rn(w.y);
        o.v[2] = __float2half_rn(w.z);
        o.v[3] = __float2half_rn(w.w);
        *(h4*)&H[i] = o;
    }
}

// ---------------- mix + fp16 convert ----------------
__global__ void __launch_bounds__(256)
mix_h(const float* __restrict__ x, const float* __restrict__ lastx,
      const float* __restrict__ tmk, const float* __restrict__ tmv,
      const float* __restrict__ tmr)
{
    const int i = blockIdx.x * blockDim.x + threadIdx.x;   // 0 .. MM*CC/4-1
    const int m = i >> 8;            // 256 float4 groups per row
    const int c4 = (i & 255) * 4;
    const int n = m >> 11;           // TT = 2048 rows per batch
    const size_t e = (size_t)m * CC + c4;

    const float4 xv = *(const float4*)&x[e];
    const float4 l4 = *(const float4*)&lastx[(size_t)n * CC + c4];
    const float4 tk = *(const float4*)&tmk[c4];
    const float4 tv = *(const float4*)&tmv[c4];
    const float4 tr = *(const float4*)&tmr[c4];

    const float xs[4] = {xv.x, xv.y, xv.z, xv.w};
    const float ls[4] = {l4.x, l4.y, l4.z, l4.w};
    const float tks[4] = {tk.x, tk.y, tk.z, tk.w};
    const float tvs[4] = {tv.x, tv.y, tv.z, tv.w};
    const float trs[4] = {tr.x, tr.y, tr.z, tr.w};

    struct h4 { __half v[4]; };
    h4 kh, vh, rh;
    #pragma unroll
    for (int q = 0; q < 4; q++) {
        kh.v[q] = __float2half_rn(xs[q] * tks[q] + ls[q] * (1.f - tks[q]));
        vh.v[q] = __float2half_rn(xs[q] * tvs[q] + ls[q] * (1.f - tvs[q]));
        rh.v[q] = __float2half_rn(xs[q] * trs[q] + ls[q] * (1.f - trs[q]));
    }
    *(h4*)&g_kh[e] = kh;
    *(h4*)&g_vh[e] = vh;
    *(h4*)&g_rh[e] = rh;
}

// ---------------- wkv scan (fp32, fused sigmoid gate, fp16 y out) ----------------
__global__ void __launch_bounds__(64)
wkv_scan(const float* __restrict__ kbuf, const float* __restrict__ vbuf,
         const float* __restrict__ rbuf,
         const float* __restrict__ time_decay, const float* __restrict__ time_first,
         const float* __restrict__ state)
{
    const int ch = blockIdx.x * blockDim.x + threadIdx.x;
    if (ch >= NB * CC) return;
    const int n = ch >> 10;
    const int c = ch & (CC - 1);

    const float u = time_first[c];
    const float w = __expf(time_decay[c]);

    const float* st = state + (size_t)n * 3 * CC;
    float a = st[c];
    float b = st[CC + c];
    float e = st[2 * CC + c];

    size_t idx = (size_t)n * TT * CC + c;
    #pragma unroll 4
    for (int t = 0; t < TT; t++, idx += CC) {
        const float kt = kbuf[idx];
        const float vt = vbuf[idx];

        const float ukt = u + kt;
        const float tau = fmaxf(ukt, e);
        const float e1  = __expf(e - tau);
        const float e2  = __expf(ukt - tau);
        const float wkv = (e1 * a + e2 * vt) / (e1 * b + e2);

        const float rr = rbuf[idx];
        const float sr = 1.f / (1.f + __expf(-rr));
        g_y[idx] = __float2half_rn(wkv * sr);

        const float we  = e - w;
        const float en  = fmaxf(we, kt);
        const float e1n = __expf(we - en);
        const float e2n = __expf(kt - en);
        a = e1n * a + e2n * vt;
        b = e1n * b + e2n;
        e = en;
    }
}

// ---------------- launch ----------------
extern "C" void kernel_launch(void* const* d_in, const int* in_sizes, int n_in,
                              void* d_out, int out_size)
{
    const float* x     = (const float*)d_in[0];
    const float* Wk    = (const float*)d_in[2];
    const float* Wv    = (const float*)d_in[3];
    const float* Wr    = (const float*)d_in[4];
    const float* Wo    = (const float*)d_in[5];
    const float* tmk   = (const float*)d_in[6];
    const float* tmv   = (const float*)d_in[7];
    const float* tmr   = (const float*)d_in[8];
    const float* td    = (const float*)d_in[9];
    const float* tf    = (const float*)d_in[10];
    const float* lastx = (const float*)d_in[11];
    const float* state = (const float*)d_in[12];
    float* out = (float*)d_out;

    float *kp, *vp, *rp;
    cudaGetSymbolAddress((void**)&kp, g_k);
    cudaGetSymbolAddress((void**)&vp, g_v);
    cudaGetSymbolAddress((void**)&rp, g_r);

    __half *kh, *vh, *rh, *yp;
    cudaGetSymbolAddress((void**)&kh, g_kh);
    cudaGetSymbolAddress((void**)&vh, g_vh);
    cudaGetSymbolAddress((void**)&rh, g_rh);
    cudaGetSymbolAddress((void**)&yp, g_y);

    __half *wkh, *wvh, *wrh, *woh;
    cudaGetSymbolAddress((void**)&wkh, g_Wkh);
    cudaGetSymbolAddress((void**)&wvh, g_Wvh);
    cudaGetSymbolAddress((void**)&wrh, g_Wrh);
    cudaGetSymbolAddress((void**)&woh, g_Woh);

    cudaFuncSetAttribute(gemm_fp16, cudaFuncAttributeMaxDynamicSharedMemorySize, GEMM_SMEM);

    const int nW = CC * CC;
    conv_w<<<(nW / 4 + 255) / 256, 256>>>(Wk, wkh, nW);
    conv_w<<<(nW / 4 + 255) / 256, 256>>>(Wv, wvh, nW);
    conv_w<<<(nW / 4 + 255) / 256, 256>>>(Wr, wrh, nW);
    conv_w<<<(nW / 4 + 255) / 256, 256>>>(Wo, woh, nW);

    mix_h<<<(MM * CC / 4 + 255) / 256, 256>>>(x, lastx, tmk, tmv, tmr);

    dim3 grid(CC / BN, MM / BM);   // (8, 128)
    gemm_fp16<<<grid, 256, GEMM_SMEM>>>(kh, wkh, kp);
    gemm_fp16<<<grid, 256, GEMM_SMEM>>>(vh, wvh, vp);
    gemm_fp16<<<grid, 256, GEMM_SMEM>>>(rh, wrh, rp);

    wkv_scan<<<(NB * CC + 63) / 64, 64>>>(kp, vp, rp, td, tf, state);

    gemm_fp16<<<grid, 256, GEMM_SMEM>>>(yp, woh, out);
}

// round 5
// speedup vs baseline: 3.0028x; 1.4363x over previous
#include <cuda_runtime.h>
#include <cuda_fp16.h>
#include <cstdint>

#define NB 8
#define TT 2048
#define CC 1024
#define MM (NB*TT)          // 16384

// ---------------- scratch (static __device__; no allocation) ----------------
__device__ __align__(256) float  g_kvr[(size_t)MM*3*CC];   // [m][k|v|r] fp32
__device__ __align__(256) __half g_kh[(size_t)MM*CC];
__device__ __align__(256) __half g_vh[(size_t)MM*CC];
__device__ __align__(256) __half g_rh[(size_t)MM*CC];
__device__ __align__(256) __half g_y [(size_t)MM*CC];

__device__ __align__(256) __half g_Wkvr[(size_t)3*CC*CC];  // [3072][1024]
__device__ __align__(256) __half g_Woh[CC*CC];

// ---------------- PTX helpers (architecture-stable, sm_80-era) ----------------
__device__ __forceinline__ uint32_t smem_u32(const void* p) {
    uint32_t a;
    asm("{ .reg .u64 t; cvta.to.shared.u64 t, %1; cvt.u32.u64 %0, t; }" : "=r"(a) : "l"(p));
    return a;
}
__device__ __forceinline__ void cp16(uint32_t saddr, const void* g) {
    asm volatile("cp.async.cg.shared.global [%0], [%1], 16;" :: "r"(saddr), "l"(g));
}
__device__ __forceinline__ void cp_commit() {
    asm volatile("cp.async.commit_group;" ::: "memory");
}
template<int N> __device__ __forceinline__ void cp_wait() {
    asm volatile("cp.async.wait_group %0;" :: "n"(N) : "memory");
}
__device__ __forceinline__ void ldsm4(uint32_t* r, uint32_t addr) {
    asm volatile("ldmatrix.sync.aligned.m8n8.x4.shared.b16 {%0,%1,%2,%3}, [%4];"
                 : "=r"(r[0]), "=r"(r[1]), "=r"(r[2]), "=r"(r[3]) : "r"(addr));
}
__device__ __forceinline__ void mma_f16(float* c, const uint32_t* a, uint32_t b0, uint32_t b1) {
    asm volatile(
        "mma.sync.aligned.m16n8k16.row.col.f32.f16.f16.f32 "
        "{%0,%1,%2,%3}, {%4,%5,%6,%7}, {%8,%9}, {%0,%1,%2,%3};"
        : "+f"(c[0]), "+f"(c[1]), "+f"(c[2]), "+f"(c[3])
        : "r"(a[0]), "r"(a[1]), "r"(a[2]), "r"(a[3]), "r"(b0), "r"(b1));
}

// ---------------- GEMM: C[m][j] = sum_c A(m,c)*W(j,c) ----------------
// CTA tile 128(M) x 256(N), BK=64. 8 warps: 2(M) x 4(N). Warp tile 64x64.
// A selected per N-tile from {A0,A1,A2} (fused k/v/r); ldc = gridDim.x*256.
#define BM 128
#define BN 256
#define BK 64
#define A_SZ (BM*128)                  // 16 KB
#define B_SZ (BN*128)                  // 32 KB
#define STAGE (A_SZ + B_SZ)            // 48 KB
#define NSTAGE 4
#define GEMM_SMEM (NSTAGE*STAGE)       // 192 KB

__global__ void __launch_bounds__(256, 1)
gemm_fp16(const __half* __restrict__ A0, const __half* __restrict__ A1,
          const __half* __restrict__ A2, const __half* __restrict__ W,
          float* __restrict__ Cout)
{
    extern __shared__ char smem[];
    const uint32_t sbase = smem_u32(smem);
    const int tid = threadIdx.x;
    const int wid = tid >> 5, lid = tid & 31;
    const int warp_m = wid >> 2, warp_n = wid & 3;
    const int M0 = blockIdx.y * BM, N0 = blockIdx.x * BN;
    const int ldc = gridDim.x * BN;

    const int sel = N0 >> 10;
    const __half* A = (sel == 0) ? A0 : (sel == 1) ? A1 : A2;

    float acc[4][8][4];
    #pragma unroll
    for (int i = 0; i < 4; i++)
        #pragma unroll
        for (int j = 0; j < 8; j++)
            #pragma unroll
            for (int q = 0; q < 4; q++) acc[i][j][q] = 0.f;

    auto load_stage = [&](int s) {
        const uint32_t base = sbase + (s & (NSTAGE - 1)) * STAGE;
        const int k0 = s * BK;
        #pragma unroll
        for (int i = 0; i < 4; i++) {                 // A: 1024 chunks
            const int c = tid + i * 256;
            const int r = c >> 3, j = c & 7;
            uint32_t off = r * 128 + j * 16;
            uint32_t sw = off ^ ((off >> 3) & 0x70);
            cp16(base + sw, (const char*)A + ((size_t)(M0 + r) * CC + k0) * 2 + j * 16);
        }
        #pragma unroll
        for (int i = 0; i < 8; i++) {                 // B: 2048 chunks
            const int c = tid + i * 256;
            const int r = c >> 3, j = c & 7;
            uint32_t off = r * 128 + j * 16;
            uint32_t sw = off ^ ((off >> 3) & 0x70);
            cp16(base + A_SZ + sw, (const char*)W + ((size_t)(N0 + r) * CC + k0) * 2 + j * 16);
        }
        cp_commit();
    };

    load_stage(0); load_stage(1); load_stage(2); load_stage(3);

    const int nk = CC / BK;   // 16
    for (int s = 0; s < nk; s++) {
        if      (s < nk - 3) cp_wait<3>();
        else if (s == nk-3)  cp_wait<2>();
        else if (s == nk-2)  cp_wait<1>();
        else                 cp_wait<0>();
        __syncthreads();

        const uint32_t bA = sbase + (s & (NSTAGE - 1)) * STAGE;
        const uint32_t bB = bA + A_SZ;

        #pragma unroll
        for (int st = 0; st < 4; st++) {              // 4 x k16
            const int cb = st * 32 + ((lid >> 4) * 16);
            uint32_t ah[4][4], bh[4][4];
            #pragma unroll
            for (int i = 0; i < 4; i++) {
                const int r = warp_m * 64 + i * 16 + (lid & 15);
                uint32_t off = r * 128 + cb;
                uint32_t sw = off ^ ((off >> 3) & 0x70);
                ldsm4(ah[i], bA + sw);
            }
            #pragma unroll
            for (int q = 0; q < 4; q++) {
                const int r = warp_n * 64 + q * 16 + (lid & 15);
                uint32_t off = r * 128 + cb;
                uint32_t sw = off ^ ((off >> 3) & 0x70);
                ldsm4(bh[q], bB + sw);
            }
            #pragma unroll
            for (int i = 0; i < 4; i++)
                #pragma unroll
                for (int j = 0; j < 8; j++) {
                    const int q = j >> 1, h = j & 1;
                    mma_f16(acc[i][j], ah[i], bh[q][h], bh[q][2 + h]);
                }
        }
        __syncthreads();
        if (s + NSTAGE < nk) load_stage(s + NSTAGE);
    }

    // epilogue
    #pragma unroll
    for (int i = 0; i < 4; i++) {
        const int row = M0 + warp_m * 64 + i * 16 + (lid >> 2);
        #pragma unroll
        for (int j = 0; j < 8; j++) {
            const int col = N0 + warp_n * 64 + j * 8 + (lid & 3) * 2;
            *(float2*)&Cout[(size_t)row * ldc + col]       = make_float2(acc[i][j][0], acc[i][j][1]);
            *(float2*)&Cout[(size_t)(row + 8) * ldc + col] = make_float2(acc[i][j][2], acc[i][j][3]);
        }
    }
}

// ---------------- weight convert fp32 -> fp16 ----------------
__global__ void __launch_bounds__(256)
conv_w(const float* __restrict__ W, __half* __restrict__ H, int n)
{
    int i = (blockIdx.x * blockDim.x + threadIdx.x) * 4;
    if (i < n) {
        const float4 w = *(const float4*)&W[i];
        struct h4 { __half v[4]; };
        h4 o;
        o.v[0] = __float2half_rn(w.x);
        o.v[1] = __float2half_rn(w.y);
        o.v[2] = __float2half_rn(w.z);
        o.v[3] = __float2half_rn(w.w);
        *(h4*)&H[i] = o;
    }
}

// ---------------- mix + fp16 convert ----------------
__global__ void __launch_bounds__(256)
mix_h(const float* __restrict__ x, const float* __restrict__ lastx,
      const float* __restrict__ tmk, const float* __restrict__ tmv,
      const float* __restrict__ tmr)
{
    const int i = blockIdx.x * blockDim.x + threadIdx.x;   // 0 .. MM*CC/4-1
    const int m = i >> 8;
    const int c4 = (i & 255) * 4;
    const int n = m >> 11;
    const size_t e = (size_t)m * CC + c4;

    const float4 xv = *(const float4*)&x[e];
    const float4 l4 = *(const float4*)&lastx[(size_t)n * CC + c4];
    const float4 tk = *(const float4*)&tmk[c4];
    const float4 tv = *(const float4*)&tmv[c4];
    const float4 tr = *(const float4*)&tmr[c4];

    const float xs[4] = {xv.x, xv.y, xv.z, xv.w};
    const float ls[4] = {l4.x, l4.y, l4.z, l4.w};
    const float tks[4] = {tk.x, tk.y, tk.z, tk.w};
    const float tvs[4] = {tv.x, tv.y, tv.z, tv.w};
    const float trs[4] = {tr.x, tr.y, tr.z, tr.w};

    struct h4 { __half v[4]; };
    h4 kh, vh, rh;
    #pragma unroll
    for (int q = 0; q < 4; q++) {
        kh.v[q] = __float2half_rn(xs[q] * tks[q] + ls[q] * (1.f - tks[q]));
        vh.v[q] = __float2half_rn(xs[q] * tvs[q] + ls[q] * (1.f - tvs[q]));
        rh.v[q] = __float2half_rn(xs[q] * trs[q] + ls[q] * (1.f - trs[q]));
    }
    *(h4*)&g_kh[e] = kh;
    *(h4*)&g_vh[e] = vh;
    *(h4*)&g_rh[e] = rh;
}

// ---------------- wkv scan (fp32, fused sigmoid gate, fp16 y out) ----------------
// kvr layout: [m][3072] = k | v | r
__global__ void __launch_bounds__(64)
wkv_scan(const float* __restrict__ kvr,
         const float* __restrict__ time_decay, const float* __restrict__ time_first,
         const float* __restrict__ state)
{
    const int ch = blockIdx.x * blockDim.x + threadIdx.x;
    if (ch >= NB * CC) return;
    const int n = ch >> 10;
    const int c = ch & (CC - 1);

    const float u = time_first[c];
    const float w = __expf(time_decay[c]);

    const float* st = state + (size_t)n * 3 * CC;
    float a = st[c];
    float b = st[CC + c];
    float e = st[2 * CC + c];

    size_t row = (size_t)n * TT;
    #pragma unroll 4
    for (int t = 0; t < TT; t++, row++) {
        const size_t base = row * (3 * CC);
        const float kt = kvr[base + c];
        const float vt = kvr[base + CC + c];
        const float rr = kvr[base + 2 * CC + c];

        const float ukt = u + kt;
        const float tau = fmaxf(ukt, e);
        const float e1  = __expf(e - tau);
        const float e2  = __expf(ukt - tau);
        const float wkv = (e1 * a + e2 * vt) / (e1 * b + e2);

        const float sr = 1.f / (1.f + __expf(-rr));
        g_y[row * CC + c] = __float2half_rn(wkv * sr);

        const float we  = e - w;
        const float en  = fmaxf(we, kt);
        const float e1n = __expf(we - en);
        const float e2n = __expf(kt - en);
        a = e1n * a + e2n * vt;
        b = e1n * b + e2n;
        e = en;
    }
}

// ---------------- launch ----------------
extern "C" void kernel_launch(void* const* d_in, const int* in_sizes, int n_in,
                              void* d_out, int out_size)
{
    const float* x     = (const float*)d_in[0];
    const float* Wk    = (const float*)d_in[2];
    const float* Wv    = (const float*)d_in[3];
    const float* Wr    = (const float*)d_in[4];
    const float* Wo    = (const float*)d_in[5];
    const float* tmk   = (const float*)d_in[6];
    const float* tmv   = (const float*)d_in[7];
    const float* tmr   = (const float*)d_in[8];
    const float* td    = (const float*)d_in[9];
    const float* tf    = (const float*)d_in[10];
    const float* lastx = (const float*)d_in[11];
    const float* state = (const float*)d_in[12];
    float* out = (float*)d_out;

    float* kvrp;
    cudaGetSymbolAddress((void**)&kvrp, g_kvr);

    __half *kh, *vh, *rh, *yp;
    cudaGetSymbolAddress((void**)&kh, g_kh);
    cudaGetSymbolAddress((void**)&vh, g_vh);
    cudaGetSymbolAddress((void**)&rh, g_rh);
    cudaGetSymbolAddress((void**)&yp, g_y);

    __half *wkvr, *woh;
    cudaGetSymbolAddress((void**)&wkvr, g_Wkvr);
    cudaGetSymbolAddress((void**)&woh, g_Woh);

    cudaFuncSetAttribute(gemm_fp16, cudaFuncAttributeMaxDynamicSharedMemorySize, GEMM_SMEM);

    const int nW = CC * CC;
    conv_w<<<(nW / 4 + 255) / 256, 256>>>(Wk, wkvr,          nW);
    conv_w<<<(nW / 4 + 255) / 256, 256>>>(Wv, wkvr + nW,     nW);
    conv_w<<<(nW / 4 + 255) / 256, 256>>>(Wr, wkvr + 2*nW,   nW);
    conv_w<<<(nW / 4 + 255) / 256, 256>>>(Wo, woh,           nW);

    mix_h<<<(MM * CC / 4 + 255) / 256, 256>>>(x, lastx, tmk, tmv, tmr);

    // fused k|v|r GEMM: N = 3072
    dim3 gkvr(3 * CC / BN, MM / BM);   // (12, 128)
    gemm_fp16<<<gkvr, 256, GEMM_SMEM>>>(kh, vh, rh, wkvr, kvrp);

    wkv_scan<<<(NB * CC + 63) / 64, 64>>>(kvrp, td, tf, state);

    // output GEMM: N = 1024 (sel always 0 -> pass yp thrice)
    dim3 gout(CC / BN, MM / BM);       // (4, 128)
    gemm_fp16<<<gout, 256, GEMM_SMEM>>>(yp, yp, yp, woh, out);
}

// round 6
// speedup vs baseline: 3.1271x; 1.0414x over previous
#include <cuda_runtime.h>
#include <cuda_fp16.h>
#include <cstdint>

#define NB 8
#define TT 2048
#define CC 1024
#define MM (NB*TT)          // 16384

// ---------------- scratch (static __device__; no allocation) ----------------
__device__ __align__(256) float  g_kvr[(size_t)MM*3*CC];   // [m][k|v|r] fp32
__device__ __align__(256) __half g_kh[(size_t)MM*CC];
__device__ __align__(256) __half g_vh[(size_t)MM*CC];
__device__ __align__(256) __half g_rh[(size_t)MM*CC];
__device__ __align__(256) __half g_y [(size_t)MM*CC];

__device__ __align__(256) __half g_Wkvr[(size_t)3*CC*CC];  // [3072][1024]
__device__ __align__(256) __half g_Woh[CC*CC];

// ---------------- PTX helpers (architecture-stable, sm_80-era) ----------------
__device__ __forceinline__ uint32_t smem_u32(const void* p) {
    uint32_t a;
    asm("{ .reg .u64 t; cvta.to.shared.u64 t, %1; cvt.u32.u64 %0, t; }" : "=r"(a) : "l"(p));
    return a;
}
__device__ __forceinline__ void cp16(uint32_t saddr, const void* g) {
    asm volatile("cp.async.cg.shared.global [%0], [%1], 16;" :: "r"(saddr), "l"(g));
}
__device__ __forceinline__ void cp_commit() {
    asm volatile("cp.async.commit_group;" ::: "memory");
}
template<int N> __device__ __forceinline__ void cp_wait() {
    asm volatile("cp.async.wait_group %0;" :: "n"(N) : "memory");
}
__device__ __forceinline__ void ldsm4(uint32_t* r, uint32_t addr) {
    asm volatile("ldmatrix.sync.aligned.m8n8.x4.shared.b16 {%0,%1,%2,%3}, [%4];"
                 : "=r"(r[0]), "=r"(r[1]), "=r"(r[2]), "=r"(r[3]) : "r"(addr));
}
__device__ __forceinline__ void mma_f16(float* c, const uint32_t* a, uint32_t b0, uint32_t b1) {
    asm volatile(
        "mma.sync.aligned.m16n8k16.row.col.f32.f16.f16.f32 "
        "{%0,%1,%2,%3}, {%4,%5,%6,%7}, {%8,%9}, {%0,%1,%2,%3};"
        : "+f"(c[0]), "+f"(c[1]), "+f"(c[2]), "+f"(c[3])
        : "r"(a[0]), "r"(a[1]), "r"(a[2]), "r"(a[3]), "r"(b0), "r"(b1));
}

// ---------------- GEMM: C[m][j] = sum_c A(m,c)*W(j,c) ----------------
// CTA tile 128x128, BK=64. 8 warps: 4(M) x 2(N), warp tile 32x64.
// 2 CTAs/SM (4 warps/SMSP). Single-barrier 3-stage cp.async pipeline.
// A selected per N-tile from {A0,A1,A2} (fused k/v/r); ldc = gridDim.x*BN.
#define BM 128
#define BN 128
#define BK 64
#define ASZ (BM*128)                   // 16 KB
#define STAGE (2*ASZ)                  // A + B = 32 KB
#define NSTAGE 3
#define GEMM_SMEM (NSTAGE*STAGE)       // 96 KB -> 2 CTAs/SM

__global__ void __launch_bounds__(256, 2)
gemm_fp16(const __half* __restrict__ A0, const __half* __restrict__ A1,
          const __half* __restrict__ A2, const __half* __restrict__ W,
          float* __restrict__ Cout)
{
    extern __shared__ char smem[];
    const uint32_t sbase = smem_u32(smem);
    const int tid = threadIdx.x;
    const int wid = tid >> 5, lid = tid & 31;
    const int warp_m = wid & 3, warp_n = wid >> 2;
    const int M0 = blockIdx.y * BM, N0 = blockIdx.x * BN;
    const int ldc = gridDim.x * BN;

    const int sel = N0 >> 10;
    const __half* A = (sel == 0) ? A0 : (sel == 1) ? A1 : A2;

    float acc[2][8][4];
    #pragma unroll
    for (int i = 0; i < 2; i++)
        #pragma unroll
        for (int j = 0; j < 8; j++)
            #pragma unroll
            for (int q = 0; q < 4; q++) acc[i][j][q] = 0.f;

    auto load_stage = [&](int s) {
        const uint32_t base = sbase + (s % NSTAGE) * STAGE;
        const int k0 = s * BK;
        #pragma unroll
        for (int i = 0; i < 4; i++) {
            const int c = tid + i * 256;          // 0..1023
            const int r = c >> 3, j = c & 7;
            uint32_t off = r * 128 + j * 16;
            uint32_t sw = off ^ ((off >> 3) & 0x70);
            cp16(base + sw,       (const char*)A + ((size_t)(M0 + r) * CC + k0) * 2 + j * 16);
            cp16(base + ASZ + sw, (const char*)W + ((size_t)(N0 + r) * CC + k0) * 2 + j * 16);
        }
        cp_commit();
    };

    load_stage(0); load_stage(1);

    const int nk = CC / BK;   // 16
    for (int s = 0; s < nk; s++) {
        if (s < nk - 1) cp_wait<1>();
        else            cp_wait<0>();
        __syncthreads();
        // buffer (s+2)%3 == (s-1)%3 was fully consumed before this barrier
        if (s + 2 < nk) load_stage(s + 2);

        const uint32_t bA = sbase + (s % NSTAGE) * STAGE;
        const uint32_t bB = bA + ASZ;

        #pragma unroll
        for (int st = 0; st < 4; st++) {          // 4 x k16
            const int cb = st * 32 + ((lid >> 4) * 16);
            uint32_t ah[2][4], bh[4][4];
            #pragma unroll
            for (int i = 0; i < 2; i++) {
                const int r = warp_m * 32 + i * 16 + (lid & 15);
                uint32_t off = r * 128 + cb;
                uint32_t sw = off ^ ((off >> 3) & 0x70);
                ldsm4(ah[i], bA + sw);
            }
            #pragma unroll
            for (int q = 0; q < 4; q++) {
                const int r = warp_n * 64 + q * 16 + (lid & 15);
                uint32_t off = r * 128 + cb;
                uint32_t sw = off ^ ((off >> 3) & 0x70);
                ldsm4(bh[q], bB + sw);
            }
            #pragma unroll
            for (int i = 0; i < 2; i++)
                #pragma unroll
                for (int j = 0; j < 8; j++) {
                    const int q = j >> 1, h = j & 1;
                    mma_f16(acc[i][j], ah[i], bh[q][h], bh[q][2 + h]);
                }
        }
    }

    // epilogue
    #pragma unroll
    for (int i = 0; i < 2; i++) {
        const int row = M0 + warp_m * 32 + i * 16 + (lid >> 2);
        #pragma unroll
        for (int j = 0; j < 8; j++) {
            const int col = N0 + warp_n * 64 + j * 8 + (lid & 3) * 2;
            *(float2*)&Cout[(size_t)row * ldc + col]       = make_float2(acc[i][j][0], acc[i][j][1]);
            *(float2*)&Cout[(size_t)(row + 8) * ldc + col] = make_float2(acc[i][j][2], acc[i][j][3]);
        }
    }
}

// ---------------- weight convert fp32 -> fp16 ----------------
__global__ void __launch_bounds__(256)
conv_w(const float* __restrict__ W, __half* __restrict__ H, int n)
{
    int i = (blockIdx.x * blockDim.x + threadIdx.x) * 4;
    if (i < n) {
        const float4 w = *(const float4*)&W[i];
        struct h4 { __half v[4]; };
        h4 o;
        o.v[0] = __float2half_rn(w.x);
        o.v[1] = __float2half_rn(w.y);
        o.v[2] = __float2half_rn(w.z);
        o.v[3] = __float2half_rn(w.w);
        *(h4*)&H[i] = o;
    }
}

// ---------------- mix + fp16 convert ----------------
__global__ void __launch_bounds__(256)
mix_h(const float* __restrict__ x, const float* __restrict__ lastx,
      const float* __restrict__ tmk, const float* __restrict__ tmv,
      const float* __restrict__ tmr)
{
    const int i = blockIdx.x * blockDim.x + threadIdx.x;   // 0 .. MM*CC/4-1
    const int m = i >> 8;
    const int c4 = (i & 255) * 4;
    const int n = m >> 11;
    const size_t e = (size_t)m * CC + c4;

    const float4 xv = *(const float4*)&x[e];
    const float4 l4 = *(const float4*)&lastx[(size_t)n * CC + c4];
    const float4 tk = *(const float4*)&tmk[c4];
    const float4 tv = *(const float4*)&tmv[c4];
    const float4 tr = *(const float4*)&tmr[c4];

    const float xs[4] = {xv.x, xv.y, xv.z, xv.w};
    const float ls[4] = {l4.x, l4.y, l4.z, l4.w};
    const float tks[4] = {tk.x, tk.y, tk.z, tk.w};
    const float tvs[4] = {tv.x, tv.y, tv.z, tv.w};
    const float trs[4] = {tr.x, tr.y, tr.z, tr.w};

    struct h4 { __half v[4]; };
    h4 kh, vh, rh;
    #pragma unroll
    for (int q = 0; q < 4; q++) {
        kh.v[q] = __float2half_rn(xs[q] * tks[q] + ls[q] * (1.f - tks[q]));
        vh.v[q] = __float2half_rn(xs[q] * tvs[q] + ls[q] * (1.f - tvs[q]));
        rh.v[q] = __float2half_rn(xs[q] * trs[q] + ls[q] * (1.f - trs[q]));
    }
    *(h4*)&g_kh[e] = kh;
    *(h4*)&g_vh[e] = vh;
    *(h4*)&g_rh[e] = rh;
}

// ---------------- wkv scan (fp32, fused sigmoid gate, fp16 y out) ----------------
// kvr layout: [m][3072] = k | v | r
__global__ void __launch_bounds__(64)
wkv_scan(const float* __restrict__ kvr,
         const float* __restrict__ time_decay, const float* __restrict__ time_first,
         const float* __restrict__ state)
{
    const int ch = blockIdx.x * blockDim.x + threadIdx.x;
    if (ch >= NB * CC) return;
    const int n = ch >> 10;
    const int c = ch & (CC - 1);

    const float u = time_first[c];
    const float w = __expf(time_decay[c]);

    const float* st = state + (size_t)n * 3 * CC;
    float a = st[c];
    float b = st[CC + c];
    float e = st[2 * CC + c];

    size_t row = (size_t)n * TT;
    #pragma unroll 4
    for (int t = 0; t < TT; t++, row++) {
        const size_t base = row * (3 * CC);
        const float kt = kvr[base + c];
        const float vt = kvr[base + CC + c];
        const float rr = kvr[base + 2 * CC + c];

        const float ukt = u + kt;
        const float tau = fmaxf(ukt, e);
        const float e1  = __expf(e - tau);
        const float e2  = __expf(ukt - tau);
        const float wkv = (e1 * a + e2 * vt) / (e1 * b + e2);

        const float sr = 1.f / (1.f + __expf(-rr));
        g_y[row * CC + c] = __float2half_rn(wkv * sr);

        const float we  = e - w;
        const float en  = fmaxf(we, kt);
        const float e1n = __expf(we - en);
        const float e2n = __expf(kt - en);
        a = e1n * a + e2n * vt;
        b = e1n * b + e2n;
        e = en;
    }
}

// ---------------- launch ----------------
extern "C" void kernel_launch(void* const* d_in, const int* in_sizes, int n_in,
                              void* d_out, int out_size)
{
    const float* x     = (const float*)d_in[0];
    const float* Wk    = (const float*)d_in[2];
    const float* Wv    = (const float*)d_in[3];
    const float* Wr    = (const float*)d_in[4];
    const float* Wo    = (const float*)d_in[5];
    const float* tmk   = (const float*)d_in[6];
    const float* tmv   = (const float*)d_in[7];
    const float* tmr   = (const float*)d_in[8];
    const float* td    = (const float*)d_in[9];
    const float* tf    = (const float*)d_in[10];
    const float* lastx = (const float*)d_in[11];
    const float* state = (const float*)d_in[12];
    float* out = (float*)d_out;

    float* kvrp;
    cudaGetSymbolAddress((void**)&kvrp, g_kvr);

    __half *kh, *vh, *rh, *yp;
    cudaGetSymbolAddress((void**)&kh, g_kh);
    cudaGetSymbolAddress((void**)&vh, g_vh);
    cudaGetSymbolAddress((void**)&rh, g_rh);
    cudaGetSymbolAddress((void**)&yp, g_y);

    __half *wkvr, *woh;
    cudaGetSymbolAddress((void**)&wkvr, g_Wkvr);
    cudaGetSymbolAddress((void**)&woh, g_Woh);

    cudaFuncSetAttribute(gemm_fp16, cudaFuncAttributeMaxDynamicSharedMemorySize, GEMM_SMEM);

    const int nW = CC * CC;
    conv_w<<<(nW / 4 + 255) / 256, 256>>>(Wk, wkvr,        nW);
    conv_w<<<(nW / 4 + 255) / 256, 256>>>(Wv, wkvr + nW,   nW);
    conv_w<<<(nW / 4 + 255) / 256, 256>>>(Wr, wkvr + 2*nW, nW);
    conv_w<<<(nW / 4 + 255) / 256, 256>>>(Wo, woh,         nW);

    mix_h<<<(MM * CC / 4 + 255) / 256, 256>>>(x, lastx, tmk, tmv, tmr);

    // fused k|v|r GEMM: N = 3072
    dim3 gkvr(3 * CC / BN, MM / BM);   // (24, 128)
    gemm_fp16<<<gkvr, 256, GEMM_SMEM>>>(kh, vh, rh, wkvr, kvrp);

    wkv_scan<<<(NB * CC + 63) / 64, 64>>>(kvrp, td, tf, state);

    // output GEMM: N = 1024 (sel always 0)
    dim3 gout(CC / BN, MM / BM);       // (8, 128)
    gemm_fp16<<<gout, 256, GEMM_SMEM>>>(yp, yp, yp, woh, out);
}

// round 10
// speedup vs baseline: 3.1401x; 1.0042x over previous
#include <cuda_runtime.h>
#include <cuda_fp16.h>
#include <cstdint>

#define NB 8
#define TT 2048
#define CC 1024
#define MM (NB*TT)          // 16384

// ---------------- scratch (static __device__; no allocation) ----------------
__device__ __align__(256) float  g_kvr[(size_t)MM*3*CC];   // [m][k|v|r] fp32
__device__ __align__(256) __half g_kh[(size_t)MM*CC];
__device__ __align__(256) __half g_vh[(size_t)MM*CC];
__device__ __align__(256) __half g_rh[(size_t)MM*CC];
__device__ __align__(256) __half g_y [(size_t)MM*CC];

__device__ __align__(256) __half g_Wkvr[(size_t)3*CC*CC];  // [3072][1024]
__device__ __align__(256) __half g_Woh[CC*CC];
__device__ int g_flags[256];                               // per-64-row completion counters

// ---------------- PTX helpers (architecture-stable, sm_80-era) ----------------
__device__ __forceinline__ uint32_t smem_u32(const void* p) {
    uint32_t a;
    asm("{ .reg .u64 t; cvta.to.shared.u64 t, %1; cvt.u32.u64 %0, t; }" : "=r"(a) : "l"(p));
    return a;
}
__device__ __forceinline__ void cp16(uint32_t saddr, const void* g) {
    asm volatile("cp.async.cg.shared.global [%0], [%1], 16;" :: "r"(saddr), "l"(g));
}
__device__ __forceinline__ void cp_commit() {
    asm volatile("cp.async.commit_group;" ::: "memory");
}
template<int N> __device__ __forceinline__ void cp_wait() {
    asm volatile("cp.async.wait_group %0;" :: "n"(N) : "memory");
}
__device__ __forceinline__ void ldsm4(uint32_t* r, uint32_t addr) {
    asm volatile("ldmatrix.sync.aligned.m8n8.x4.shared.b16 {%0,%1,%2,%3}, [%4];"
                 : "=r"(r[0]), "=r"(r[1]), "=r"(r[2]), "=r"(r[3]) : "r"(addr));
}
__device__ __forceinline__ void mma_f16(float* c, const uint32_t* a, uint32_t b0, uint32_t b1) {
    asm volatile(
        "mma.sync.aligned.m16n8k16.row.col.f32.f16.f16.f32 "
        "{%0,%1,%2,%3}, {%4,%5,%6,%7}, {%8,%9}, {%0,%1,%2,%3};"
        : "+f"(c[0]), "+f"(c[1]), "+f"(c[2]), "+f"(c[3])
        : "r"(a[0]), "r"(a[1]), "r"(a[2]), "r"(a[3]), "r"(b0), "r"(b1));
}

// ---------------- fused GEMM (+ optional scan blocks) ----------------
// GEMM: C[m][j] = sum_c A(m,c)*W(j,c). CTA tile 64(M)x128(N), BK=64.
// 8 warps: 2(M) x 4(N), warp tile 32x32. 3-stage single-barrier pipeline.
// Blocks [0, nscan) run the wkv scan, spinning on g_flags rowblock counters.
#define BM 64
#define BN 128
#define BK 64
#define A_SZ (BM*128)                  // 8 KB
#define B_SZ (BN*128)                  // 16 KB
#define STAGE (A_SZ + B_SZ)            // 24 KB
#define NSTAGE 3
#define GEMM_SMEM (NSTAGE*STAGE)       // 72 KB

__global__ void __launch_bounds__(256, 3)
fused_gemm(const __half* __restrict__ A0, const __half* __restrict__ A1,
           const __half* __restrict__ A2, const __half* __restrict__ W,
           float* __restrict__ Cout, int tiles_x, int nscan, int set_flags,
           const float* __restrict__ td, const float* __restrict__ tf,
           const float* __restrict__ state)
{
    const int tid = threadIdx.x;

    // ---------------- scan role ----------------
    if ((int)blockIdx.x < nscan) {
        const int ch = blockIdx.x * 256 + tid;        // 0..8191, all same batch per block
        const int n = ch >> 10;
        const int c = ch & (CC - 1);

        const float u = tf[c];
        const float w = __expf(td[c]);

        const float* st = state + (size_t)n * 3 * CC;
        float a = st[c];
        float b = st[CC + c];
        float e = st[2 * CC + c];

        const size_t row0 = (size_t)n * TT;
        for (int t0 = 0; t0 < TT; t0 += 64) {
            const int rb = (int)((row0 + t0) >> 6);
            if (tid == 0) {
                while (atomicAdd(&g_flags[rb], 0) < tiles_x) __nanosleep(128);
            }
            __syncthreads();
            __threadfence();

            size_t base3 = (row0 + t0) * (3 * CC);
            size_t basey = (row0 + t0) * CC + c;
            #pragma unroll 4
            for (int t = 0; t < 64; t++, base3 += 3 * CC, basey += CC) {
                const float kt = __ldcg(&g_kvr[base3 + c]);
                const float vt = __ldcg(&g_kvr[base3 + CC + c]);
                const float rr = __ldcg(&g_kvr[base3 + 2 * CC + c]);

                const float ukt = u + kt;
                const float tau = fmaxf(ukt, e);
                const float e1  = __expf(e - tau);
                const float e2  = __expf(ukt - tau);
                const float wkv = (e1 * a + e2 * vt) / (e1 * b + e2);

                const float sr = 1.f / (1.f + __expf(-rr));
                g_y[basey] = __float2half_rn(wkv * sr);

                const float we  = e - w;
                const float en  = fmaxf(we, kt);
                const float e1n = __expf(we - en);
                const float e2n = __expf(kt - en);
                a = e1n * a + e2n * vt;
                b = e1n * b + e2n;
                e = en;
            }
        }
        return;
    }

    // ---------------- GEMM role ----------------
    extern __shared__ char smem[];
    const uint32_t sbase = smem_u32(smem);
    const int wid = tid >> 5, lid = tid & 31;
    const int warp_m = wid & 1, warp_n = wid >> 1;
    const int t = blockIdx.x - nscan;
    const int bx = t % tiles_x, by = t / tiles_x;
    const int M0 = by * BM, N0 = bx * BN;
    const int ldc = tiles_x * BN;

    const int sel = N0 >> 10;
    const __half* A = (sel == 0) ? A0 : (sel == 1) ? A1 : A2;

    float acc[2][4][4];
    #pragma unroll
    for (int i = 0; i < 2; i++)
        #pragma unroll
        for (int j = 0; j < 4; j++)
            #pragma unroll
            for (int q = 0; q < 4; q++) acc[i][j][q] = 0.f;

    auto load_stage = [&](int s) {
        const uint32_t base = sbase + (s % NSTAGE) * STAGE;
        const int k0 = s * BK;
        #pragma unroll
        for (int i = 0; i < 2; i++) {                 // A: 512 chunks
            const int c = tid + i * 256;
            const int r = c >> 3, j = c & 7;
            uint32_t off = r * 128 + j * 16;
            uint32_t sw = off ^ ((off >> 3) & 0x70);
            cp16(base + sw, (const char*)A + ((size_t)(M0 + r) * CC + k0) * 2 + j * 16);
        }
        #pragma unroll
        for (int i = 0; i < 4; i++) {                 // B: 1024 chunks
            const int c = tid + i * 256;
            const int r = c >> 3, j = c & 7;
            uint32_t off = r * 128 + j * 16;
            uint32_t sw = off ^ ((off >> 3) & 0x70);
            cp16(base + A_SZ + sw, (const char*)W + ((size_t)(N0 + r) * CC + k0) * 2 + j * 16);
        }
        cp_commit();
    };

    load_stage(0); load_stage(1);

    const int nk = CC / BK;   // 16
    for (int s = 0; s < nk; s++) {
        if (s < nk - 1) cp_wait<1>();
        else            cp_wait<0>();
        __syncthreads();
        if (s + 2 < nk) load_stage(s + 2);

        const uint32_t bA = sbase + (s % NSTAGE) * STAGE;
        const uint32_t bB = bA + A_SZ;

        #pragma unroll
        for (int st = 0; st < 4; st++) {              // 4 x k16
            const int cb = st * 32 + ((lid >> 4) * 16);
            uint32_t ah[2][4], bh[2][4];
            #pragma unroll
            for (int i = 0; i < 2; i++) {
                const int r = warp_m * 32 + i * 16 + (lid & 15);
                uint32_t off = r * 128 + cb;
                uint32_t sw = off ^ ((off >> 3) & 0x70);
                ldsm4(ah[i], bA + sw);
            }
            #pragma unroll
            for (int q = 0; q < 2; q++) {
                const int r = warp_n * 32 + q * 16 + (lid & 15);
                uint32_t off = r * 128 + cb;
                uint32_t sw = off ^ ((off >> 3) & 0x70);
                ldsm4(bh[q], bB + sw);
            }
            #pragma unroll
            for (int i = 0; i < 2; i++)
                #pragma unroll
                for (int j = 0; j < 4; j++) {
                    const int q = j >> 1, h = j & 1;
                    mma_f16(acc[i][j], ah[i], bh[q][h], bh[q][2 + h]);
                }
        }
    }

    // epilogue
    #pragma unroll
    for (int i = 0; i < 2; i++) {
        const int row = M0 + warp_m * 32 + i * 16 + (lid >> 2);
        #pragma unroll
        for (int j = 0; j < 4; j++) {
            const int col = N0 + warp_n * 32 + j * 8 + (lid & 3) * 2;
            *(float2*)&Cout[(size_t)row * ldc + col]       = make_float2(acc[i][j][0], acc[i][j][1]);
            *(float2*)&Cout[(size_t)(row + 8) * ldc + col] = make_float2(acc[i][j][2], acc[i][j][3]);
        }
    }

    if (set_flags) {
        __threadfence();
        __syncthreads();
        if (tid == 0) atomicAdd(&g_flags[by], 1);
    }
}

// ---------------- merged weight convert (also zeroes flags) ----------------
__global__ void __launch_bounds__(256)
conv_all(const float* __restrict__ Wk, const float* __restrict__ Wv,
         const float* __restrict__ Wr, const float* __restrict__ Wo)
{
    if (blockIdx.x == 0) g_flags[threadIdx.x] = 0;   // 256 flags

    const size_t gid = (size_t)blockIdx.x * blockDim.x + threadIdx.x;  // 1M threads
    const int mat = (int)(gid >> 18);                // 256K threads per matrix
    const size_t off = (gid & 0x3FFFF) * 4;
    const float* src = (mat == 0) ? Wk : (mat == 1) ? Wv : (mat == 2) ? Wr : Wo;
    __half* dst = (mat < 3) ? (g_Wkvr + (size_t)mat * CC * CC) : g_Woh;

    const float4 w = *(const float4*)&src[off];
    struct h4 { __half v[4]; };
    h4 o;
    o.v[0] = __float2half_rn(w.x);
    o.v[1] = __float2half_rn(w.y);
    o.v[2] = __float2half_rn(w.z);
    o.v[3] = __float2half_rn(w.w);
    *(h4*)&dst[off] = o;
}

// ---------------- mix + fp16 convert ----------------
__global__ void __launch_bounds__(256)
mix_h(const float* __restrict__ x, const float* __restrict__ lastx,
      const float* __restrict__ tmk, const float* __restrict__ tmv,
      const float* __restrict__ tmr)
{
    const int i = blockIdx.x * blockDim.x + threadIdx.x;   // 0 .. MM*CC/4-1
    const int m = i >> 8;
    const int c4 = (i & 255) * 4;
    const int n = m >> 11;
    const size_t e = (size_t)m * CC + c4;

    const float4 xv = *(const float4*)&x[e];
    const float4 l4 = *(const float4*)&lastx[(size_t)n * CC + c4];
    const float4 tk = *(const float4*)&tmk[c4];
    const float4 tv = *(const float4*)&tmv[c4];
    const float4 tr = *(const float4*)&tmr[c4];

    const float xs[4] = {xv.x, xv.y, xv.z, xv.w};
    const float ls[4] = {l4.x, l4.y, l4.z, l4.w};
    const float tks[4] = {tk.x, tk.y, tk.z, tk.w};
    const float tvs[4] = {tv.x, tv.y, tv.z, tv.w};
    const float trs[4] = {tr.x, tr.y, tr.z, tr.w};

    struct h4 { __half v[4]; };
    h4 kh, vh, rh;
    #pragma unroll
    for (int q = 0; q < 4; q++) {
        kh.v[q] = __float2half_rn(xs[q] * tks[q] + ls[q] * (1.f - tks[q]));
        vh.v[q] = __float2half_rn(xs[q] * tvs[q] + ls[q] * (1.f - tvs[q]));
        rh.v[q] = __float2half_rn(xs[q] * trs[q] + ls[q] * (1.f - trs[q]));
    }
    *(h4*)&g_kh[e] = kh;
    *(h4*)&g_vh[e] = vh;
    *(h4*)&g_rh[e] = rh;
}

// ---------------- launch ----------------
extern "C" void kernel_launch(void* const* d_in, const int* in_sizes, int n_in,
                              void* d_out, int out_size)
{
    const float* x     = (const float*)d_in[0];
    const float* Wk    = (const float*)d_in[2];
    const float* Wv    = (const float*)d_in[3];
    const float* Wr    = (const float*)d_in[4];
    const float* Wo    = (const float*)d_in[5];
    const float* tmk   = (const float*)d_in[6];
    const float* tmv   = (const float*)d_in[7];
    const float* tmr   = (const float*)d_in[8];
    const float* td    = (const float*)d_in[9];
    const float* tf    = (const float*)d_in[10];
    const float* lastx = (const float*)d_in[11];
    const float* state = (const float*)d_in[12];
    float* out = (float*)d_out;

    float* kvrp;
    cudaGetSymbolAddress((void**)&kvrp, g_kvr);

    __half *kh, *vh, *rh, *yp;
    cudaGetSymbolAddress((void**)&kh, g_kh);
    cudaGetSymbolAddress((void**)&vh, g_vh);
    cudaGetSymbolAddress((void**)&rh, g_rh);
    cudaGetSymbolAddress((void**)&yp, g_y);

    __half *wkvr, *woh;
    cudaGetSymbolAddress((void**)&wkvr, g_Wkvr);
    cudaGetSymbolAddress((void**)&woh, g_Woh);

    cudaFuncSetAttribute(fused_gemm, cudaFuncAttributeMaxDynamicSharedMemorySize, GEMM_SMEM);

    // merged weight convert + flag zeroing: 4M elems / 4 per thread / 256 = 4096 blocks
    conv_all<<<4096, 256>>>(Wk, Wv, Wr, Wo);

    mix_h<<<(MM * CC / 4 + 255) / 256, 256>>>(x, lastx, tmk, tmv, tmr);

    // fused k|v|r GEMM (tiles 24 x 256 = 6144) + 32 scan blocks
    const int kvr_tx = 3 * CC / BN;            // 24
    const int kvr_blocks = kvr_tx * (MM / BM); // 6144
    fused_gemm<<<32 + kvr_blocks, 256, GEMM_SMEM>>>(
        kh, vh, rh, wkvr, kvrp, kvr_tx, 32, 1, td, tf, state);

    // output GEMM: tiles 8 x 256 = 2048, no scan, no flags
    const int out_tx = CC / BN;                // 8
    fused_gemm<<<out_tx * (MM / BM), 256, GEMM_SMEM>>>(
        yp, yp, yp, woh, out, out_tx, 0, 0, td, tf, state);
}

// round 12
// speedup vs baseline: 6.3866x; 2.0339x over previous
#include <cuda_runtime.h>
#include <cuda_fp16.h>
#include <cstdint>

#define NB 8
#define TT 2048
#define CC 1024
#define MM (NB*TT)          // 16384

// ---------------- scratch (static __device__; no allocation) ----------------
__device__ __align__(256) float  g_kvr[(size_t)MM*3*CC];   // [m][k|v|r] fp32
__device__ __align__(256) __half g_kh[(size_t)MM*CC];
__device__ __align__(256) __half g_vh[(size_t)MM*CC];
__device__ __align__(256) __half g_rh[(size_t)MM*CC];
__device__ __align__(256) __half g_y [(size_t)MM*CC];

__device__ __align__(256) __half g_Wkvr[(size_t)3*CC*CC];  // [3072][1024]
__device__ __align__(256) __half g_Woh[CC*CC];
// flags[0..255]   : kvr rowblock (64 rows) completion, counts to 24 tiles
// flags[256..511] : y rowblock completion, counts to 4 scan blocks
__device__ int g_flags[512];

// ---------------- PTX helpers (architecture-stable, sm_80-era) ----------------
__device__ __forceinline__ uint32_t smem_u32(const void* p) {
    uint32_t a;
    asm("{ .reg .u64 t; cvta.to.shared.u64 t, %1; cvt.u32.u64 %0, t; }" : "=r"(a) : "l"(p));
    return a;
}
__device__ __forceinline__ void cp16(uint32_t saddr, const void* g) {
    asm volatile("cp.async.cg.shared.global [%0], [%1], 16;" :: "r"(saddr), "l"(g));
}
__device__ __forceinline__ void cp_commit() {
    asm volatile("cp.async.commit_group;" ::: "memory");
}
template<int N> __device__ __forceinline__ void cp_wait() {
    asm volatile("cp.async.wait_group %0;" :: "n"(N) : "memory");
}
__device__ __forceinline__ void ldsm4(uint32_t* r, uint32_t addr) {
    asm volatile("ldmatrix.sync.aligned.m8n8.x4.shared.b16 {%0,%1,%2,%3}, [%4];"
                 : "=r"(r[0]), "=r"(r[1]), "=r"(r[2]), "=r"(r[3]) : "r"(addr));
}
__device__ __forceinline__ void mma_f16(float* c, const uint32_t* a, uint32_t b0, uint32_t b1) {
    asm volatile(
        "mma.sync.aligned.m16n8k16.row.col.f32.f16.f16.f32 "
        "{%0,%1,%2,%3}, {%4,%5,%6,%7}, {%8,%9}, {%0,%1,%2,%3};"
        : "+f"(c[0]), "+f"(c[1]), "+f"(c[2]), "+f"(c[3])
        : "r"(a[0]), "r"(a[1]), "r"(a[2]), "r"(a[3]), "r"(b0), "r"(b1));
}

// ---------------- tiling ----------------
#define BM 64
#define BN 128
#define BK 64
#define A_SZ (BM*128)                  // 8 KB
#define B_SZ (BN*128)                  // 16 KB
#define STAGE (A_SZ + B_SZ)            // 24 KB
#define NSTAGE 3
#define GEMM_SMEM (NSTAGE*STAGE)       // 72 KB -> 3 CTAs/SM

#define NSCAN 32
#define KVR_TX 24
#define KVR_TILES (KVR_TX*(MM/BM))     // 6144
#define OUT_TX 8
#define OUT_TILES (OUT_TX*(MM/BM))     // 2048

// ---------------- GEMM role (device) ----------------
__device__ __forceinline__ void gemm_role(
    int t, int tiles_x,
    const __half* __restrict__ A, const __half* __restrict__ W,
    float* __restrict__ Cout, int ldc,
    int wait_y, int set_kvr, char* smem, int tid)
{
    const uint32_t sbase = smem_u32(smem);
    const int wid = tid >> 5, lid = tid & 31;
    const int warp_m = wid & 1, warp_n = wid >> 1;
    const int bx = t % tiles_x, by = t / tiles_x;
    const int M0 = by * BM, N0 = bx * BN;

    if (wait_y) {     // out-GEMM: wait for scan to finish this 64-row chunk of y
        if (tid == 0) {
            while (atomicAdd(&g_flags[256 + by], 0) < 4) __nanosleep(256);
        }
        __syncthreads();
        __threadfence();
    }

    float acc[2][4][4];
    #pragma unroll
    for (int i = 0; i < 2; i++)
        #pragma unroll
        for (int j = 0; j < 4; j++)
            #pragma unroll
            for (int q = 0; q < 4; q++) acc[i][j][q] = 0.f;

    auto load_stage = [&](int s) {
        const uint32_t base = sbase + (s % NSTAGE) * STAGE;
        const int k0 = s * BK;
        #pragma unroll
        for (int i = 0; i < 2; i++) {                 // A: 512 chunks
            const int c = tid + i * 256;
            const int r = c >> 3, j = c & 7;
            uint32_t off = r * 128 + j * 16;
            uint32_t sw = off ^ ((off >> 3) & 0x70);
            cp16(base + sw, (const char*)A + ((size_t)(M0 + r) * CC + k0) * 2 + j * 16);
        }
        #pragma unroll
        for (int i = 0; i < 4; i++) {                 // B: 1024 chunks
            const int c = tid + i * 256;
            const int r = c >> 3, j = c & 7;
            uint32_t off = r * 128 + j * 16;
            uint32_t sw = off ^ ((off >> 3) & 0x70);
            cp16(base + A_SZ + sw, (const char*)W + ((size_t)(N0 + r) * CC + k0) * 2 + j * 16);
        }
        cp_commit();
    };

    load_stage(0); load_stage(1);

    const int nk = CC / BK;   // 16
    for (int s = 0; s < nk; s++) {
        if (s < nk - 1) cp_wait<1>();
        else            cp_wait<0>();
        __syncthreads();
        if (s + 2 < nk) load_stage(s + 2);

        const uint32_t bA = sbase + (s % NSTAGE) * STAGE;
        const uint32_t bB = bA + A_SZ;

        #pragma unroll
        for (int st = 0; st < 4; st++) {              // 4 x k16
            const int cb = st * 32 + ((lid >> 4) * 16);
            uint32_t ah[2][4], bh[2][4];
            #pragma unroll
            for (int i = 0; i < 2; i++) {
                const int r = warp_m * 32 + i * 16 + (lid & 15);
                uint32_t off = r * 128 + cb;
                uint32_t sw = off ^ ((off >> 3) & 0x70);
                ldsm4(ah[i], bA + sw);
            }
            #pragma unroll
            for (int q = 0; q < 2; q++) {
                const int r = warp_n * 32 + q * 16 + (lid & 15);
                uint32_t off = r * 128 + cb;
                uint32_t sw = off ^ ((off >> 3) & 0x70);
                ldsm4(bh[q], bB + sw);
            }
            #pragma unroll
            for (int i = 0; i < 2; i++)
                #pragma unroll
                for (int j = 0; j < 4; j++) {
                    const int q = j >> 1, h = j & 1;
                    mma_f16(acc[i][j], ah[i], bh[q][h], bh[q][2 + h]);
                }
        }
    }

    // epilogue
    #pragma unroll
    for (int i = 0; i < 2; i++) {
        const int row = M0 + warp_m * 32 + i * 16 + (lid >> 2);
        #pragma unroll
        for (int j = 0; j < 4; j++) {
            const int col = N0 + warp_n * 32 + j * 8 + (lid & 3) * 2;
            *(float2*)&Cout[(size_t)row * ldc + col]       = make_float2(acc[i][j][0], acc[i][j][1]);
            *(float2*)&Cout[(size_t)(row + 8) * ldc + col] = make_float2(acc[i][j][2], acc[i][j][3]);
        }
    }

    if (set_kvr) {
        __threadfence();
        __syncthreads();
        if (tid == 0) atomicAdd(&g_flags[by], 1);
    }
}

// ---------------- scan role (device): software-pipelined prefetch ----------------
#define PD 8
__device__ __forceinline__ void scan_role(
    int bi, int tid,
    const float* __restrict__ td, const float* __restrict__ tf,
    const float* __restrict__ state)
{
    const int ch = bi * 256 + tid;          // 0..8191; one block = one batch slice
    const int n = ch >> 10;
    const int c = ch & (CC - 1);

    const float u = tf[c];
    const float w = __expf(td[c]);

    const float* st = state + (size_t)n * 3 * CC;
    float a = st[c];
    float b = st[CC + c];
    float e = st[2 * CC + c];

    const size_t row0 = (size_t)n * TT;
    float kq[PD], vq[PD], rq[PD];

    for (int t0 = 0; t0 < TT; t0 += 64) {
        const int rb = n * 32 + (t0 >> 6);            // global 64-row block index
        if (tid == 0) {
            while (atomicAdd(&g_flags[rb], 0) < KVR_TX) __nanosleep(128);
        }
        __syncthreads();
        __threadfence();

        const size_t rbase = row0 + t0;
        #pragma unroll
        for (int d = 0; d < PD; d++) {
            const size_t b3 = (rbase + d) * (3 * CC);
            kq[d] = __ldcg(&g_kvr[b3 + c]);
            vq[d] = __ldcg(&g_kvr[b3 + CC + c]);
            rq[d] = __ldcg(&g_kvr[b3 + 2 * CC + c]);
        }

        #pragma unroll 8
        for (int t = 0; t < 64; t++) {
            const float kt = kq[t & (PD-1)];
            const float vt = vq[t & (PD-1)];
            const float rr = rq[t & (PD-1)];
            if (t < 64 - PD) {
                const size_t b3 = (rbase + t + PD) * (3 * CC);
                kq[t & (PD-1)] = __ldcg(&g_kvr[b3 + c]);
                vq[t & (PD-1)] = __ldcg(&g_kvr[b3 + CC + c]);
                rq[t & (PD-1)] = __ldcg(&g_kvr[b3 + 2 * CC + c]);
            }

            const float ukt = u + kt;
            const float tau = fmaxf(ukt, e);
            const float e1  = __expf(e - tau);
            const float e2  = __expf(ukt - tau);
            const float wkv = (e1 * a + e2 * vt) / (e1 * b + e2);

            const float sr = 1.f / (1.f + __expf(-rr));
            g_y[(rbase + t) * CC + c] = __float2half_rn(wkv * sr);

            const float we  = e - w;
            const float en  = fmaxf(we, kt);
            const float e1n = __expf(we - en);
            const float e2n = __expf(kt - en);
            a = e1n * a + e2n * vt;
            b = e1n * b + e2n;
            e = en;
        }

        __threadfence();
        __syncthreads();
        if (tid == 0) atomicAdd(&g_flags[256 + rb], 1);   // 4 blocks per rowblock
    }
}

// ---------------- mega kernel: scan | kvr GEMM | out GEMM ----------------
__global__ void __launch_bounds__(256, 3)
mega(const __half* __restrict__ A0, const __half* __restrict__ A1,
     const __half* __restrict__ A2, const __half* __restrict__ Wkvr,
     float* __restrict__ Ckvr,
     const __half* __restrict__ Ay, const __half* __restrict__ Wo,
     float* __restrict__ Cout,
     const float* __restrict__ td, const float* __restrict__ tf,
     const float* __restrict__ state)
{
    extern __shared__ char smem[];
    const int tid = threadIdx.x;
    const int bi = blockIdx.x;

    if (bi < NSCAN) {
        scan_role(bi, tid, td, tf, state);
    } else if (bi < NSCAN + KVR_TILES) {
        const int t = bi - NSCAN;
        const int sel = ((t % KVR_TX) * BN) >> 10;
        const __half* A = (sel == 0) ? A0 : (sel == 1) ? A1 : A2;
        gemm_role(t, KVR_TX, A, Wkvr, Ckvr, KVR_TX * BN, 0, 1, smem, tid);
    } else {
        const int t = bi - NSCAN - KVR_TILES;
        gemm_role(t, OUT_TX, Ay, Wo, Cout, OUT_TX * BN, 1, 0, smem, tid);
    }
}

// ---------------- merged weight convert (also zeroes flags) ----------------
__global__ void __launch_bounds__(256)
conv_all(const float* __restrict__ Wk, const float* __restrict__ Wv,
         const float* __restrict__ Wr, const float* __restrict__ Wo)
{
    if (blockIdx.x < 2) g_flags[blockIdx.x * 256 + threadIdx.x] = 0;   // 512 flags

    const size_t gid = (size_t)blockIdx.x * blockDim.x + threadIdx.x;  // 1M threads
    const int mat = (int)(gid >> 18);                // 256K threads per matrix
    const size_t off = (gid & 0x3FFFF) * 4;
    const float* src = (mat == 0) ? Wk : (mat == 1) ? Wv : (mat == 2) ? Wr : Wo;
    __half* dst = (mat < 3) ? (g_Wkvr + (size_t)mat * CC * CC) : g_Woh;

    const float4 w = *(const float4*)&src[off];
    struct h4 { __half v[4]; };
    h4 o;
    o.v[0] = __float2half_rn(w.x);
    o.v[1] = __float2half_rn(w.y);
    o.v[2] = __float2half_rn(w.z);
    o.v[3] = __float2half_rn(w.w);
    *(h4*)&dst[off] = o;
}

// ---------------- mix + fp16 convert ----------------
__global__ void __launch_bounds__(256)
mix_h(const float* __restrict__ x, const float* __restrict__ lastx,
      const float* __restrict__ tmk, const float* __restrict__ tmv,
      const float* __restrict__ tmr)
{
    const int i = blockIdx.x * blockDim.x + threadIdx.x;   // 0 .. MM*CC/4-1
    const int m = i >> 8;
    const int c4 = (i & 255) * 4;
    const int n = m >> 11;
    const size_t e = (size_t)m * CC + c4;

    const float4 xv = *(const float4*)&x[e];
    const float4 l4 = *(const float4*)&lastx[(size_t)n * CC + c4];
    const float4 tk = *(const float4*)&tmk[c4];
    const float4 tv = *(const float4*)&tmv[c4];
    const float4 tr = *(const float4*)&tmr[c4];

    const float xs[4] = {xv.x, xv.y, xv.z, xv.w};
    const float ls[4] = {l4.x, l4.y, l4.z, l4.w};
    const float tks[4] = {tk.x, tk.y, tk.z, tk.w};
    const float tvs[4] = {tv.x, tv.y, tv.z, tv.w};
    const float trs[4] = {tr.x, tr.y, tr.z, tr.w};

    struct h4 { __half v[4]; };
    h4 kh, vh, rh;
    #pragma unroll
    for (int q = 0; q < 4; q++) {
        kh.v[q] = __float2half_rn(xs[q] * tks[q] + ls[q] * (1.f - tks[q]));
        vh.v[q] = __float2half_rn(xs[q] * tvs[q] + ls[q] * (1.f - tvs[q]));
        rh.v[q] = __float2half_rn(xs[q] * trs[q] + ls[q] * (1.f - trs[q]));
    }
    *(h4*)&g_kh[e] = kh;
    *(h4*)&g_vh[e] = vh;
    *(h4*)&g_rh[e] = rh;
}

// ---------------- launch ----------------
extern "C" void kernel_launch(void* const* d_in, const int* in_sizes, int n_in,
                              void* d_out, int out_size)
{
    const float* x     = (const float*)d_in[0];
    const float* Wk    = (const float*)d_in[2];
    const float* Wv    = (const float*)d_in[3];
    const float* Wr    = (const float*)d_in[4];
    const float* Wo    = (const float*)d_in[5];
    const float* tmk   = (const float*)d_in[6];
    const float* tmv   = (const float*)d_in[7];
    const float* tmr   = (const float*)d_in[8];
    const float* td    = (const float*)d_in[9];
    const float* tf    = (const float*)d_in[10];
    const float* lastx = (const float*)d_in[11];
    const float* state = (const float*)d_in[12];
    float* out = (float*)d_out;

    float* kvrp;
    cudaGetSymbolAddress((void**)&kvrp, g_kvr);

    __half *kh, *vh, *rh, *yp;
    cudaGetSymbolAddress((void**)&kh, g_kh);
    cudaGetSymbolAddress((void**)&vh, g_vh);
    cudaGetSymbolAddress((void**)&rh, g_rh);
    cudaGetSymbolAddress((void**)&yp, g_y);

    __half *wkvr, *woh;
    cudaGetSymbolAddress((void**)&wkvr, g_Wkvr);
    cudaGetSymbolAddress((void**)&woh, g_Woh);

    cudaFuncSetAttribute(mega, cudaFuncAttributeMaxDynamicSharedMemorySize, GEMM_SMEM);

    // merged weight convert + flag zeroing
    conv_all<<<4096, 256>>>(Wk, Wv, Wr, Wo);

    mix_h<<<(MM * CC / 4 + 255) / 256, 256>>>(x, lastx, tmk, tmv, tmr);

    // one mega kernel: 32 scan + 6144 kvr-GEMM + 2048 out-GEMM blocks
    mega<<<NSCAN + KVR_TILES + OUT_TILES, 256, GEMM_SMEM>>>(
        kh, vh, rh, wkvr, kvrp, yp, woh, out, td, tf, state);
}

// round 16
// speedup vs baseline: 6.7742x; 1.0607x over previous
#include <cuda_runtime.h>
#include <cuda_fp16.h>
#include <cstdint>

#define NB 8
#define TT 2048
#define CC 1024
#define MM (NB*TT)          // 16384

// ---------------- scratch (static __device__; no allocation) ----------------
__device__ __align__(256) float  g_kvr[(size_t)MM*3*CC];   // [m][k|v|r] fp32
__device__ __align__(256) __half g_kh[(size_t)MM*CC];
__device__ __align__(256) __half g_vh[(size_t)MM*CC];
__device__ __align__(256) __half g_rh[(size_t)MM*CC];
__device__ __align__(256) __half g_y [(size_t)MM*CC];

__device__ __align__(256) __half g_Wkvr[(size_t)3*CC*CC];  // [3072][1024]
__device__ __align__(256) __half g_Woh[CC*CC];
// flags[0..127]   : kvr rowblock (128 rows) completion, counts to 24 tiles
// flags[256..383] : y rowblock completion, counts to 4 scan blocks
__device__ int g_flags[512];

// ---------------- PTX helpers (architecture-stable, sm_80-era) ----------------
__device__ __forceinline__ uint32_t smem_u32(const void* p) {
    uint32_t a;
    asm("{ .reg .u64 t; cvta.to.shared.u64 t, %1; cvt.u32.u64 %0, t; }" : "=r"(a) : "l"(p));
    return a;
}
__device__ __forceinline__ void cp16(uint32_t saddr, const void* g) {
    asm volatile("cp.async.cg.shared.global [%0], [%1], 16;" :: "r"(saddr), "l"(g));
}
__device__ __forceinline__ void cp_commit() {
    asm volatile("cp.async.commit_group;" ::: "memory");
}
template<int N> __device__ __forceinline__ void cp_wait() {
    asm volatile("cp.async.wait_group %0;" :: "n"(N) : "memory");
}
__device__ __forceinline__ void ldsm4(uint32_t* r, uint32_t addr) {
    asm volatile("ldmatrix.sync.aligned.m8n8.x4.shared.b16 {%0,%1,%2,%3}, [%4];"
                 : "=r"(r[0]), "=r"(r[1]), "=r"(r[2]), "=r"(r[3]) : "r"(addr));
}
__device__ __forceinline__ void mma_f16(float* c, const uint32_t* a, uint32_t b0, uint32_t b1) {
    asm volatile(
        "mma.sync.aligned.m16n8k16.row.col.f32.f16.f16.f32 "
        "{%0,%1,%2,%3}, {%4,%5,%6,%7}, {%8,%9}, {%0,%1,%2,%3};"
        : "+f"(c[0]), "+f"(c[1]), "+f"(c[2]), "+f"(c[3])
        : "r"(a[0]), "r"(a[1]), "r"(a[2]), "r"(a[3]), "r"(b0), "r"(b1));
}

// ---------------- tiling ----------------
#define BM 128
#define BN 128
#define BK 64
#define A_SZ (BM*128)                  // 16 KB
#define B_SZ (BN*128)                  // 16 KB
#define STAGE (A_SZ + B_SZ)            // 32 KB
#define NSTAGE 3
#define GEMM_SMEM (NSTAGE*STAGE)       // 96 KB -> 2 CTAs/SM

#define NSCAN 32
#define KVR_TX 24
#define KVR_TILES (KVR_TX*(MM/BM))     // 3072
#define OUT_TX 8
#define OUT_TILES (OUT_TX*(MM/BM))     // 1024

// ---------------- GEMM role (device) ----------------
// 8 warps: 4(M) x 2(N), warp tile 32x64. Single-barrier 3-stage pipeline.
__device__ __forceinline__ void gemm_role(
    int t, int tiles_x,
    const __half* __restrict__ A, const __half* __restrict__ W,
    float* __restrict__ Cout, int ldc,
    int wait_y, int set_kvr, char* smem, int tid)
{
    const uint32_t sbase = smem_u32(smem);
    const int wid = tid >> 5, lid = tid & 31;
    const int warp_m = wid & 3, warp_n = wid >> 2;
    const int bx = t % tiles_x, by = t / tiles_x;
    const int M0 = by * BM, N0 = bx * BN;

    if (wait_y) {     // out-GEMM: wait for scan to finish this 128-row chunk of y
        if (tid == 0) {
            while (atomicAdd(&g_flags[256 + by], 0) < 4) __nanosleep(256);
        }
        __syncthreads();
        __threadfence();
    }

    float acc[2][8][4];
    #pragma unroll
    for (int i = 0; i < 2; i++)
        #pragma unroll
        for (int j = 0; j < 8; j++)
            #pragma unroll
            for (int q = 0; q < 4; q++) acc[i][j][q] = 0.f;

    auto load_stage = [&](int s) {
        const uint32_t base = sbase + (s % NSTAGE) * STAGE;
        const int k0 = s * BK;
        #pragma unroll
        for (int i = 0; i < 4; i++) {                 // A: 1024 chunks
            const int c = tid + i * 256;
            const int r = c >> 3, j = c & 7;
            uint32_t off = r * 128 + j * 16;
            uint32_t sw = off ^ ((off >> 3) & 0x70);
            cp16(base + sw,        (const char*)A + ((size_t)(M0 + r) * CC + k0) * 2 + j * 16);
            cp16(base + A_SZ + sw, (const char*)W + ((size_t)(N0 + r) * CC + k0) * 2 + j * 16);
        }
        cp_commit();
    };

    load_stage(0); load_stage(1);

    const int nk = CC / BK;   // 16
    for (int s = 0; s < nk; s++) {
        if (s < nk - 1) cp_wait<1>();
        else            cp_wait<0>();
        __syncthreads();
        if (s + 2 < nk) load_stage(s + 2);

        const uint32_t bA = sbase + (s % NSTAGE) * STAGE;
        const uint32_t bB = bA + A_SZ;

        #pragma unroll
        for (int st = 0; st < 4; st++) {              // 4 x k16
            const int cb = st * 32 + ((lid >> 4) * 16);
            uint32_t ah[2][4], bh[4][4];
            #pragma unroll
            for (int i = 0; i < 2; i++) {
                const int r = warp_m * 32 + i * 16 + (lid & 15);
                uint32_t off = r * 128 + cb;
                uint32_t sw = off ^ ((off >> 3) & 0x70);
                ldsm4(ah[i], bA + sw);
            }
            #pragma unroll
            for (int q = 0; q < 4; q++) {
                const int r = warp_n * 64 + q * 16 + (lid & 15);
                uint32_t off = r * 128 + cb;
                uint32_t sw = off ^ ((off >> 3) & 0x70);
                ldsm4(bh[q], bB + sw);
            }
            #pragma unroll
            for (int i = 0; i < 2; i++)
                #pragma unroll
                for (int j = 0; j < 8; j++) {
                    const int q = j >> 1, h = j & 1;
                    mma_f16(acc[i][j], ah[i], bh[q][h], bh[q][2 + h]);
                }
        }
    }

    // epilogue
    #pragma unroll
    for (int i = 0; i < 2; i++) {
        const int row = M0 + warp_m * 32 + i * 16 + (lid >> 2);
        #pragma unroll
        for (int j = 0; j < 8; j++) {
            const int col = N0 + warp_n * 64 + j * 8 + (lid & 3) * 2;
            *(float2*)&Cout[(size_t)row * ldc + col]       = make_float2(acc[i][j][0], acc[i][j][1]);
            *(float2*)&Cout[(size_t)(row + 8) * ldc + col] = make_float2(acc[i][j][2], acc[i][j][3]);
        }
    }

    if (set_kvr) {
        __threadfence();
        __syncthreads();
        if (tid == 0) atomicAdd(&g_flags[by], 1);
    }
}

// ---------------- scan role (device): software-pipelined prefetch ----------------
#define PD 8
__device__ __forceinline__ void scan_role(
    int bi, int tid,
    const float* __restrict__ td, const float* __restrict__ tf,
    const float* __restrict__ state)
{
    const int ch = bi * 256 + tid;          // 0..8191; one block = quarter batch
    const int n = ch >> 10;
    const int c = ch & (CC - 1);

    const float u = tf[c];
    const float w = __expf(td[c]);

    const float* st = state + (size_t)n * 3 * CC;
    float a = st[c];
    float b = st[CC + c];
    float e = st[2 * CC + c];

    const size_t row0 = (size_t)n * TT;
    float kq[PD], vq[PD], rq[PD];

    for (int t0 = 0; t0 < TT; t0 += BM) {             // 128-row chunks
        const int rb = n * (TT / BM) + (t0 / BM);     // global 128-row block index
        if (tid == 0) {
            while (atomicAdd(&g_flags[rb], 0) < KVR_TX) __nanosleep(128);
        }
        __syncthreads();
        __threadfence();

        const size_t rbase = row0 + t0;
        #pragma unroll
        for (int d = 0; d < PD; d++) {
            const size_t b3 = (rbase + d) * (3 * CC);
            kq[d] = __ldcg(&g_kvr[b3 + c]);
            vq[d] = __ldcg(&g_kvr[b3 + CC + c]);
            rq[d] = __ldcg(&g_kvr[b3 + 2 * CC + c]);
        }

        #pragma unroll 8
        for (int t = 0; t < BM; t++) {
            const float kt = kq[t & (PD-1)];
            const float vt = vq[t & (PD-1)];
            const float rr = rq[t & (PD-1)];
            if (t < BM - PD) {
                const size_t b3 = (rbase + t + PD) * (3 * CC);
                kq[t & (PD-1)] = __ldcg(&g_kvr[b3 + c]);
                vq[t & (PD-1)] = __ldcg(&g_kvr[b3 + CC + c]);
                rq[t & (PD-1)] = __ldcg(&g_kvr[b3 + 2 * CC + c]);
            }

            const float ukt = u + kt;
            const float tau = fmaxf(ukt, e);
            const float e1  = __expf(e - tau);
            const float e2  = __expf(ukt - tau);
            const float wkv = (e1 * a + e2 * vt) / (e1 * b + e2);

            const float sr = 1.f / (1.f + __expf(-rr));
            g_y[(rbase + t) * CC + c] = __float2half_rn(wkv * sr);

            const float we  = e - w;
            const float en  = fmaxf(we, kt);
            const float e1n = __expf(we - en);
            const float e2n = __expf(kt - en);
            a = e1n * a + e2n * vt;
            b = e1n * b + e2n;
            e = en;
        }

        __threadfence();
        __syncthreads();
        if (tid == 0) atomicAdd(&g_flags[256 + rb], 1);   // 4 scan blocks per batch
    }
}

// ---------------- mega kernel: scan | kvr GEMM | out GEMM ----------------
__global__ void __launch_bounds__(256, 2)
mega(const __half* __restrict__ A0, const __half* __restrict__ A1,
     const __half* __restrict__ A2, const __half* __restrict__ Wkvr,
     float* __restrict__ Ckvr,
     const __half* __restrict__ Ay, const __half* __restrict__ Wo,
     float* __restrict__ Cout,
     const float* __restrict__ td, const float* __restrict__ tf,
     const float* __restrict__ state)
{
    extern __shared__ char smem[];
    const int tid = threadIdx.x;
    const int bi = blockIdx.x;

    if (bi < NSCAN) {
        scan_role(bi, tid, td, tf, state);
    } else if (bi < NSCAN + KVR_TILES) {
        const int t = bi - NSCAN;
        const int sel = ((t % KVR_TX) * BN) >> 10;
        const __half* A = (sel == 0) ? A0 : (sel == 1) ? A1 : A2;
        gemm_role(t, KVR_TX, A, Wkvr, Ckvr, KVR_TX * BN, 0, 1, smem, tid);
    } else {
        const int t = bi - NSCAN - KVR_TILES;
        gemm_role(t, OUT_TX, Ay, Wo, Cout, OUT_TX * BN, 1, 0, smem, tid);
    }
}

// ---------------- merged weight convert (also zeroes flags) ----------------
__global__ void __launch_bounds__(256)
conv_all(const float* __restrict__ Wk, const float* __restrict__ Wv,
         const float* __restrict__ Wr, const float* __restrict__ Wo)
{
    if (blockIdx.x < 2) g_flags[blockIdx.x * 256 + threadIdx.x] = 0;   // 512 flags

    const size_t gid = (size_t)blockIdx.x * blockDim.x + threadIdx.x;  // 1M threads
    const int mat = (int)(gid >> 18);                // 256K threads per matrix
    const size_t off = (gid & 0x3FFFF) * 4;
    const float* src = (mat == 0) ? Wk : (mat == 1) ? Wv : (mat == 2) ? Wr : Wo;
    __half* dst = (mat < 3) ? (g_Wkvr + (size_t)mat * CC * CC) : g_Woh;

    const float4 w = *(const float4*)&src[off];
    struct h4 { __half v[4]; };
    h4 o;
    o.v[0] = __float2half_rn(w.x);
    o.v[1] = __float2half_rn(w.y);
    o.v[2] = __float2half_rn(w.z);
    o.v[3] = __float2half_rn(w.w);
    *(h4*)&dst[off] = o;
}

// ---------------- mix + fp16 convert ----------------
__global__ void __launch_bounds__(256)
mix_h(const float* __restrict__ x, const float* __restrict__ lastx,
      const float* __restrict__ tmk, const float* __restrict__ tmv,
      const float* __restrict__ tmr)
{
    const int i = blockIdx.x * blockDim.x + threadIdx.x;   // 0 .. MM*CC/4-1
    const int m = i >> 8;
    const int c4 = (i & 255) * 4;
    const int n = m >> 11;
    const size_t e = (size_t)m * CC + c4;

    const float4 xv = *(const float4*)&x[e];
    const float4 l4 = *(const float4*)&lastx[(size_t)n * CC + c4];
    const float4 tk = *(const float4*)&tmk[c4];
    const float4 tv = *(const float4*)&tmv[c4];
    const float4 tr = *(const float4*)&tmr[c4];

    const float xs[4] = {xv.x, xv.y, xv.z, xv.w};
    const float ls[4] = {l4.x, l4.y, l4.z, l4.w};
    const float tks[4] = {tk.x, tk.y, tk.z, tk.w};
    const float tvs[4] = {tv.x, tv.y, tv.z, tv.w};
    const float trs[4] = {tr.x, tr.y, tr.z, tr.w};

    struct h4 { __half v[4]; };
    h4 kh, vh, rh;
    #pragma unroll
    for (int q = 0; q < 4; q++) {
        kh.v[q] = __float2half_rn(xs[q] * tks[q] + ls[q] * (1.f - tks[q]));
        vh.v[q] = __float2half_rn(xs[q] * tvs[q] + ls[q] * (1.f - tvs[q]));
        rh.v[q] = __float2half_rn(xs[q] * trs[q] + ls[q] * (1.f - trs[q]));
    }
    *(h4*)&g_kh[e] = kh;
    *(h4*)&g_vh[e] = vh;
    *(h4*)&g_rh[e] = rh;
}

// ---------------- launch ----------------
extern "C" void kernel_launch(void* const* d_in, const int* in_sizes, int n_in,
                              void* d_out, int out_size)
{
    const float* x     = (const float*)d_in[0];
    const float* Wk    = (const float*)d_in[2];
    const float* Wv    = (const float*)d_in[3];
    const float* Wr    = (const float*)d_in[4];
    const float* Wo    = (const float*)d_in[5];
    const float* tmk   = (const float*)d_in[6];
    const float* tmv   = (const float*)d_in[7];
    const float* tmr   = (const float*)d_in[8];
    const float* td    = (const float*)d_in[9];
    const float* tf    = (const float*)d_in[10];
    const float* lastx = (const float*)d_in[11];
    const float* state = (const float*)d_in[12];
    float* out = (float*)d_out;

    float* kvrp;
    cudaGetSymbolAddress((void**)&kvrp, g_kvr);

    __half *kh, *vh, *rh, *yp;
    cudaGetSymbolAddress((void**)&kh, g_kh);
    cudaGetSymbolAddress((void**)&vh, g_vh);
    cudaGetSymbolAddress((void**)&rh, g_rh);
    cudaGetSymbolAddress((void**)&yp, g_y);

    __half *wkvr, *woh;
    cudaGetSymbolAddress((void**)&wkvr, g_Wkvr);
    cudaGetSymbolAddress((void**)&woh, g_Woh);

    cudaFuncSetAttribute(mega, cudaFuncAttributeMaxDynamicSharedMemorySize, GEMM_SMEM);

    // merged weight convert + flag zeroing
    conv_all<<<4096, 256>>>(Wk, Wv, Wr, Wo);

    mix_h<<<(MM * CC / 4 + 255) / 256, 256>>>(x, lastx, tmk, tmv, tmr);

    // one mega kernel: 32 scan + 3072 kvr-GEMM + 1024 out-GEMM blocks
    mega<<<NSCAN + KVR_TILES + OUT_TILES, 256, GEMM_SMEM>>>(
        kh, vh, rh, wkvr, kvrp, yp, woh, out, td, tf, state);
}